// round 9
// baseline (speedup 1.0000x reference)
#include <cuda_runtime.h>
#include <cuda_fp16.h>
#include <math.h>
#include <stdint.h>

#define Nn   32
#define Cc   192
#define Tt   256
#define Vv   25
#define Ss   3
#define MID  64
#define TV   6400          /* T*V */
#define C3   576           /* 3*C */
#define KF   1600          /* MID*Vv flattened contraction for attention */

// Scratch (static device arrays; allocation-free per harness rules)
__device__ __align__(16) __half g_xt16[(size_t)Nn * TV * Cc];        // x^T [n][p][c]
__device__ __align__(16) __half g_win16[C3 * Cc];                    // w_in fp16
__device__ __align__(16) __half g_qk[(size_t)Nn * 2 * Ss * Tt * KF]; // Q,K [n][part][s][t][kf]
__device__ __align__(16) __half g_vt16[(size_t)Nn * Ss * KF * Tt];   // V^T [n][s][j][t]
__device__ __align__(16) __half g_att16[(size_t)Nn * Ss * Tt * Tt];  // [ns][t][q]
__device__ __align__(16) float  g_y[(size_t)Nn * Cc * TV];           // [n][d][p] tf32-rounded

// ---------------------------------------------------------------------------
// helpers
// ---------------------------------------------------------------------------
__device__ __forceinline__ uint32_t f2tf32(float x) {
    uint32_t r;
    asm("cvt.rna.tf32.f32 %0, %1;" : "=r"(r) : "f"(x));
    return r;
}
__device__ __forceinline__ float rnd_tf32(float x) {
    return __uint_as_float(f2tf32(x));
}
__device__ __forceinline__ void mma_tf32(float* d, const uint32_t* a,
                                         uint32_t b0, uint32_t b1) {
    asm volatile(
        "mma.sync.aligned.m16n8k8.row.col.f32.tf32.tf32.f32 "
        "{%0,%1,%2,%3}, {%4,%5,%6,%7}, {%8,%9}, {%0,%1,%2,%3};"
        : "+f"(d[0]), "+f"(d[1]), "+f"(d[2]), "+f"(d[3])
        : "r"(a[0]), "r"(a[1]), "r"(a[2]), "r"(a[3]), "r"(b0), "r"(b1));
}
__device__ __forceinline__ void mma_f16(float* d, const uint32_t* a,
                                        uint32_t b0, uint32_t b1) {
    asm volatile(
        "mma.sync.aligned.m16n8k16.row.col.f32.f16.f16.f32 "
        "{%0,%1,%2,%3}, {%4,%5,%6,%7}, {%8,%9}, {%0,%1,%2,%3};"
        : "+f"(d[0]), "+f"(d[1]), "+f"(d[2]), "+f"(d[3])
        : "r"(a[0]), "r"(a[1]), "r"(a[2]), "r"(a[3]), "r"(b0), "r"(b1));
}
__device__ __forceinline__ uint32_t smem_u32(const void* p) {
    return (uint32_t)__cvta_generic_to_shared(p);
}
__device__ __forceinline__ void cp16(uint32_t dst, const void* src) {
    asm volatile("cp.async.cg.shared.global [%0], [%1], 16;"
                 :: "r"(dst), "l"(src));
}
#define CP_COMMIT() asm volatile("cp.async.commit_group;")
#define CP_WAIT1()  asm volatile("cp.async.wait_group 1;" ::: "memory")

// ---------------------------------------------------------------------------
// fp16 tile format (validated R7/R8): [row][16 halves] = 8 b32/row;
// 16B granule u of row r stored at granule (u ^ ((r>>2)&1)).
// Warp tile 32m x 64n, BK=16, acc[2][8][4].
// ---------------------------------------------------------------------------
__device__ __forceinline__ void mma16_chunk(const uint32_t* __restrict__ As,
                                            const uint32_t* __restrict__ Bs,
                                            float acc[2][8][4],
                                            int m0, int n0, int g, int ltg) {
    const int xk = 4 * ((g >> 2) & 1);
    const int ka = ltg + xk;
    const int kb = ltg + (xk ^ 4);
    uint32_t a[2][4];
#pragma unroll
    for (int mt = 0; mt < 2; mt++) {
        const uint32_t* Ar = As + (m0 + mt * 16 + g) * 8;
        a[mt][0] = Ar[ka];
        a[mt][1] = Ar[64 + ka];
        a[mt][2] = Ar[kb];
        a[mt][3] = Ar[64 + kb];
    }
#pragma unroll
    for (int nt = 0; nt < 8; nt++) {
        const uint32_t* Br = Bs + (n0 + nt * 8 + g) * 8;
        const uint32_t b0 = Br[ka];
        const uint32_t b1 = Br[kb];
        mma_f16(acc[0][nt], a[0], b0, b1);
        mma_f16(acc[1][nt], a[1], b0, b1);
    }
}
__device__ __forceinline__ int sw_off(int r, int au) {
    return r * 8 + (au ^ ((r >> 2) & 1)) * 4;
}

// TF32 fragment math for k_ff (identical to R8).
template <int SBN, bool CA, bool CB>
__device__ __forceinline__ void mma_AkBn(const float* __restrict__ As,
                                         const float* __restrict__ Bs,
                                         float acc[2][8][4],
                                         int m0, int n0, int g, int ltg) {
    const int xk = 4 * ((g >> 1) & 3);
#pragma unroll
    for (int k8 = 0; k8 < 16; k8 += 8) {
        const int ka = (k8 + ltg) ^ xk;
        const int kb = (k8 + ltg + 4) ^ xk;
        uint32_t a[2][4];
#pragma unroll
        for (int mt = 0; mt < 2; mt++) {
            const float* Ar = As + (m0 + mt * 16 + g) * 16;
            a[mt][0] = CA ? f2tf32(Ar[ka]) : __float_as_uint(Ar[ka]);
            a[mt][1] = CA ? f2tf32(Ar[128 + ka]) : __float_as_uint(Ar[128 + ka]);
            a[mt][2] = CA ? f2tf32(Ar[kb]) : __float_as_uint(Ar[kb]);
            a[mt][3] = CA ? f2tf32(Ar[128 + kb]) : __float_as_uint(Ar[128 + kb]);
        }
        const float* B0 = Bs + (k8 + ltg) * SBN + n0 + g;
        const float* B1 = Bs + (k8 + ltg + 4) * SBN + n0 + g;
#pragma unroll
        for (int nt = 0; nt < 8; nt++) {
            const uint32_t b0 = CB ? f2tf32(B0[nt * 8]) : __float_as_uint(B0[nt * 8]);
            const uint32_t b1 = CB ? f2tf32(B1[nt * 8]) : __float_as_uint(B1[nt * 8]);
            mma_tf32(acc[0][nt], a[0], b0, b1);
            mma_tf32(acc[1][nt], a[1], b0, b1);
        }
    }
}

// ---------------------------------------------------------------------------
// Kernel 0a: w_in -> fp16.
// ---------------------------------------------------------------------------
__global__ void k_wcv(const float* __restrict__ w_in) {
    const int i = blockIdx.x * 256 + threadIdx.x;
    if (i < C3 * Cc) g_win16[i] = __float2half(w_in[i]);
}

// ---------------------------------------------------------------------------
// Kernel 0b: transpose-convert x [n][c][p] fp32 -> xt16 [n][p][c] fp16.
// Block handles 64 p x 192 c; coalesced reads + coalesced b32 writes.
// ---------------------------------------------------------------------------
__global__ __launch_bounds__(256) void k_cvtx(const float* __restrict__ x) {
    __shared__ uint32_t sm[64 * 97];
    const int n = blockIdx.y, p0 = blockIdx.x * 64;
    const float* xn = x + (size_t)n * Cc * TV;
    for (int idx = threadIdx.x; idx < 96 * 64; idx += 256) {
        const int c2 = idx >> 6, p = idx & 63;
        const float f0 = xn[(size_t)(2 * c2) * TV + p0 + p];
        const float f1 = xn[(size_t)(2 * c2 + 1) * TV + p0 + p];
        const __half2 h = __floats2half2_rn(f0, f1);
        sm[p * 97 + c2] = *(const uint32_t*)&h;
    }
    __syncthreads();
    uint32_t* dst = (uint32_t*)g_xt16 + ((size_t)n * TV + p0) * (Cc / 2);
    for (int idx = threadIdx.x; idx < 64 * 96; idx += 256) {
        const int p = idx / 96, u = idx - p * 96;
        dst[(size_t)p * 96 + u] = sm[p * 97 + u];
    }
}

// ---------------------------------------------------------------------------
// Kernel 1: QKV projection, full fp16 MMA. Block 64(d) x 256(p), K=192.
// A = w_in16[d][c], B = xt16[p][c]. Epilogue: Q,K token-major fp16;
// V -> V^T fp16 via smem transpose + run-contiguous stores.
// ---------------------------------------------------------------------------
__global__ __launch_bounds__(256, 2) void k_qkv(const float* __restrict__ b_in) {
    __shared__ __align__(16) uint32_t raw[8448];   // 33792 B
    uint32_t* AsP = raw;                            // 2 x 512
    uint32_t* BsP = raw + 1024;                     // 2 x 2048
    __half*  vt  = (__half*)raw;                    // epilogue alias (64 x 264)

    const int n  = blockIdx.z;
    const int d0 = blockIdx.x * 64;
    const int p0 = blockIdx.y * 256;
    const int tid = threadIdx.x, warp = tid >> 5, lane = tid & 31;
    const int wm = warp >> 2, wn = warp & 3;
    const int g = lane >> 2, ltg = lane & 3;

    const int r2 = tid >> 1, au = tid & 1;

    auto stage = [&](int buf, int k0) {
        if (tid < 128)
            cp16(smem_u32(AsP + buf * 512 + sw_off(r2, au)),
                 g_win16 + (size_t)(d0 + r2) * Cc + k0 + au * 8);
#pragma unroll
        for (int i = 0; i < 2; i++) {
            const int p = r2 + 128 * i;
            cp16(smem_u32(BsP + buf * 2048 + sw_off(p, au)),
                 g_xt16 + ((size_t)n * TV + p0 + p) * Cc + k0 + au * 8);
        }
    };

    float acc[2][8][4] = {};
    stage(0, 0);
    CP_COMMIT();
    const int NC = Cc / 16;   // 12
#pragma unroll 1
    for (int c = 0; c < NC; c++) {
        if (c + 1 < NC) stage((c + 1) & 1, (c + 1) * 16);
        CP_COMMIT();
        CP_WAIT1();
        __syncthreads();
        mma16_chunk(AsP + (c & 1) * 512, BsP + (c & 1) * 2048, acc,
                    wm * 32, wn * 64, g, ltg);
        __syncthreads();
    }

    const int part = d0 / Cc;           // 0=Q,1=K,2=V
    const int s = (d0 % Cc) / MID;
    if (part < 2) {
        __half* qk = g_qk + (((size_t)(n * 2 + part) * Ss + s) * Tt) * KF;
#pragma unroll
        for (int mt = 0; mt < 2; mt++)
#pragma unroll
            for (int half = 0; half < 2; half++) {
                const int cch = wm * 32 + mt * 16 + g + half * 8;
                const float bias = b_in[d0 + cch];
#pragma unroll
                for (int nt = 0; nt < 8; nt++)
#pragma unroll
                    for (int e = 0; e < 2; e++) {
                        const int p = p0 + wn * 64 + nt * 8 + ltg * 2 + e;
                        const int t = p / 25, v = p - t * 25;
                        qk[(size_t)t * KF + cch * 25 + v] =
                            __float2half(acc[mt][nt][half * 2 + e] + bias);
                    }
            }
    } else {
        // dump to smem tile [c 64][poff 264-stride]
#pragma unroll
        for (int mt = 0; mt < 2; mt++)
#pragma unroll
            for (int half = 0; half < 2; half++) {
                const int cch = wm * 32 + mt * 16 + g + half * 8;
                const float bias = b_in[d0 + cch];
#pragma unroll
                for (int nt = 0; nt < 8; nt++) {
                    const int poff = wn * 64 + nt * 8 + ltg * 2;
                    __half2 hv = __floats2half2_rn(
                        acc[mt][nt][half * 2 + 0] + bias,
                        acc[mt][nt][half * 2 + 1] + bias);
                    *(__half2*)&vt[cch * 264 + poff] = hv;
                }
            }
        __syncthreads();
        // write V^T rows: j = c*25+v, contiguous t-runs
        __half* vb = g_vt16 + ((size_t)(n * Ss + s) * KF) * Tt;
        for (int j = tid; j < KF; j += 256) {
            const int c = j / 25, v = j - c * 25;
            const int tlo = (p0 + 24 - v) / 25;
            const int thi = (p0 + 256 + 24 - v) / 25;
            __half* dst = vb + (size_t)j * Tt;
            const __half* srow = vt + c * 264 - p0 + v;
            for (int t = tlo; t < thi; t++)
                dst[t] = srow[t * 25];
        }
    }
}

// ---------------------------------------------------------------------------
// Kernel 2: att = tanh(Q K^T / 1600). fp16 MMA, fp16 output.
// ---------------------------------------------------------------------------
__global__ __launch_bounds__(256, 2) void k_att() {
    __shared__ __align__(16) uint32_t As[2][64 * 8];
    __shared__ __align__(16) uint32_t Bs[2][256 * 8];
    const int ns = blockIdx.z;
    const int n = ns / 3, s = ns - 3 * n;
    const int t0 = blockIdx.y * 64;
    const int tid = threadIdx.x, warp = tid >> 5, lane = tid & 31;
    const int wm = warp >> 2, wn = warp & 3;
    const int g = lane >> 2, ltg = lane & 3;

    const __half* Qb = g_qk + (((size_t)(n * 2 + 0) * Ss + s) * Tt) * KF;
    const __half* Kb = g_qk + (((size_t)(n * 2 + 1) * Ss + s) * Tt) * KF;

    const int r2 = tid >> 1, au = tid & 1;

    auto stage = [&](int buf, int k0) {
        if (tid < 128)
            cp16(smem_u32(&As[buf][sw_off(r2, au)]),
                 Qb + (size_t)(t0 + r2) * KF + k0 + au * 8);
#pragma unroll
        for (int i = 0; i < 2; i++) {
            const int q = r2 + 128 * i;
            cp16(smem_u32(&Bs[buf][sw_off(q, au)]),
                 Kb + (size_t)q * KF + k0 + au * 8);
        }
    };

    float acc[2][8][4] = {};
    stage(0, 0);
    CP_COMMIT();
    const int NC = KF / 16;
#pragma unroll 1
    for (int c = 0; c < NC; c++) {
        if (c + 1 < NC) stage((c + 1) & 1, (c + 1) * 16);
        CP_COMMIT();
        CP_WAIT1();
        __syncthreads();
        mma16_chunk(As[c & 1], Bs[c & 1], acc, wm * 32, wn * 64, g, ltg);
        __syncthreads();
    }

    const float scale = 1.0f / (float)KF;
    __half* arow = g_att16 + (size_t)ns * Tt * Tt;
#pragma unroll
    for (int mt = 0; mt < 2; mt++)
#pragma unroll
        for (int half = 0; half < 2; half++) {
            const int t = t0 + wm * 32 + mt * 16 + g + half * 8;
#pragma unroll
            for (int nt = 0; nt < 8; nt++) {
                const int q = wn * 64 + nt * 8 + ltg * 2;
                __half2 o = __floats2half2_rn(
                    tanhf(acc[mt][nt][half * 2 + 0] * scale),
                    tanhf(acc[mt][nt][half * 2 + 1] * scale));
                *(__half2*)&arow[(size_t)t * Tt + q] = o;
            }
        }
}

// ---------------------------------------------------------------------------
// Kernel 3: y = att @ V. fp16 MMA. A = att16[t][q], B = vt16[j][t(=k)].
// Block 256(t, 8 warps) x 64(j), K=256. Output fp32 y[c][p] (tf32-rounded).
// ---------------------------------------------------------------------------
__global__ __launch_bounds__(256, 2) void k_y() {
    __shared__ __align__(16) uint32_t As[2][256 * 8];
    __shared__ __align__(16) uint32_t Bs[2][64 * 8];
    const int ns = blockIdx.z;
    const int n = ns / 3, s = ns - 3 * n;
    const int j0 = blockIdx.x * 64;
    const int tid = threadIdx.x, warp = tid >> 5, lane = tid & 31;
    const int g = lane >> 2, ltg = lane & 3;

    const __half* att = g_att16 + (size_t)ns * Tt * Tt;
    const __half* Vb  = g_vt16 + ((size_t)(n * Ss + s) * KF) * Tt;

    const int r2 = tid >> 1, au = tid & 1;

    auto stage = [&](int buf, int k0) {
#pragma unroll
        for (int i = 0; i < 2; i++) {
            const int t = r2 + 128 * i;
            cp16(smem_u32(&As[buf][sw_off(t, au)]),
                 att + (size_t)t * Tt + k0 + au * 8);
        }
        if (tid < 128)
            cp16(smem_u32(&Bs[buf][sw_off(r2, au)]),
                 Vb + (size_t)(j0 + r2) * Tt + k0 + au * 8);
    };

    float acc[2][8][4] = {};
    stage(0, 0);
    CP_COMMIT();
    const int NC = Tt / 16;
#pragma unroll 1
    for (int c = 0; c < NC; c++) {
        if (c + 1 < NC) stage((c + 1) & 1, (c + 1) * 16);
        CP_COMMIT();
        CP_WAIT1();
        __syncthreads();
        mma16_chunk(As[c & 1], Bs[c & 1], acc, warp * 32, 0, g, ltg);
        __syncthreads();
    }

    float* yb = g_y + (size_t)n * Cc * TV + (size_t)(s * MID) * TV;
#pragma unroll
    for (int mt = 0; mt < 2; mt++)
#pragma unroll
        for (int half = 0; half < 2; half++) {
            const int t = warp * 32 + mt * 16 + g + half * 8;
#pragma unroll
            for (int nt = 0; nt < 8; nt++)
#pragma unroll
                for (int e = 0; e < 2; e++) {
                    const int j = j0 + nt * 8 + ltg * 2 + e;
                    const int cch = j / 25, v = j - cch * 25;
                    yb[(size_t)cch * TV + t * 25 + v] =
                        rnd_tf32(acc[mt][nt][half * 2 + e]);
                }
        }
}

// ---------------------------------------------------------------------------
// Kernel 4: FF + BN + residual + LeakyReLU (TF32, identical to R8).
// ---------------------------------------------------------------------------
__global__ __launch_bounds__(256, 2) void k_ff(const float* __restrict__ x,
                                               const float* __restrict__ w_ff,
                                               const float* __restrict__ b_ff,
                                               const float* __restrict__ gamma,
                                               const float* __restrict__ beta,
                                               const float* __restrict__ mean,
                                               const float* __restrict__ var,
                                               float* __restrict__ out) {
    __shared__ __align__(16) float As[2][64 * 16];
    __shared__ __align__(16) float Bs[2][16 * 264];
    const int n  = blockIdx.z;
    const int d0 = blockIdx.x * 64;
    const int p0 = blockIdx.y * 256;
    const int tid = threadIdx.x, warp = tid >> 5, lane = tid & 31;
    const int wm = warp >> 2, wn = warp & 3;
    const int g = lane >> 2, ltg = lane & 3;

    const float* yn = g_y + (size_t)n * Cc * TV;

    const int ar = tid >> 2, au = tid & 3;
    const int axc = 4 * (au ^ ((ar >> 1) & 3));
    const int br = tid >> 4, bc4 = (tid & 15) * 4;

    auto stage = [&](int buf, int k0) {
        cp16(smem_u32(&As[buf][ar * 16 + axc]),
             &w_ff[(size_t)(d0 + ar) * Cc + k0 + au * 4]);
        const float* src = &yn[(size_t)(k0 + br) * TV + p0 + bc4];
        float* dst = &Bs[buf][br * 264 + bc4];
#pragma unroll
        for (int u = 0; u < 4; u++)
            cp16(smem_u32(dst + u * 64), src + u * 64);
    };

    float acc[2][8][4] = {};
    stage(0, 0);
    CP_COMMIT();
    const int NC = Cc / 16;
#pragma unroll 1
    for (int c = 0; c < NC; c++) {
        if (c + 1 < NC) stage((c + 1) & 1, (c + 1) * 16);
        CP_COMMIT();
        CP_WAIT1();
        __syncthreads();
        mma_AkBn<264, true, false>(As[c & 1], Bs[c & 1], acc,
                                   wm * 32, wn * 64, g, ltg);
        __syncthreads();
    }

    const float* xn = x + (size_t)n * Cc * TV;
    float* on = out + (size_t)n * Cc * TV;
#pragma unroll
    for (int mt = 0; mt < 2; mt++)
#pragma unroll
        for (int half = 0; half < 2; half++) {
            const int d = d0 + wm * 32 + mt * 16 + g + half * 8;
            const float inv = gamma[d] * rsqrtf(var[d] + 1e-5f);
            const float add = (b_ff[d] - mean[d]) * inv + beta[d];
#pragma unroll
            for (int nt = 0; nt < 8; nt++) {
                const int p = p0 + wn * 64 + nt * 8 + ltg * 2;
                const size_t off = (size_t)d * TV + p;
                float2 xv = *(const float2*)&xn[off];
                float z0 = xv.x + acc[mt][nt][half * 2 + 0] * inv + add;
                float z1 = xv.y + acc[mt][nt][half * 2 + 1] * inv + add;
                float2 o;
                o.x = z0 >= 0.f ? z0 : 0.1f * z0;
                o.y = z1 >= 0.f ? z1 : 0.1f * z1;
                *(float2*)&on[off] = o;
            }
        }
}

// ---------------------------------------------------------------------------
extern "C" void kernel_launch(void* const* d_in, const int* in_sizes, int n_in,
                              void* d_out, int out_size) {
    (void)in_sizes; (void)n_in; (void)out_size;
    const float* x     = (const float*)d_in[0];
    const float* w_in  = (const float*)d_in[1];
    const float* b_in  = (const float*)d_in[2];
    const float* w_ff  = (const float*)d_in[3];
    const float* b_ff  = (const float*)d_in[4];
    const float* gamma = (const float*)d_in[5];
    const float* beta  = (const float*)d_in[6];
    const float* mean  = (const float*)d_in[7];
    const float* var   = (const float*)d_in[8];
    float* out = (float*)d_out;

    k_wcv <<<(C3 * Cc + 255) / 256, 256>>>(w_in);
    k_cvtx<<<dim3(TV / 64, Nn), 256>>>(x);
    k_qkv <<<dim3(C3 / 64, TV / 256, Nn), 256>>>(b_in);
    k_att <<<dim3(1, Tt / 64, Nn * Ss), 256>>>();
    k_y   <<<dim3(KF / 64, 1, Nn * Ss), 256>>>();
    k_ff  <<<dim3(Cc / 64, TV / 256, Nn), 256>>>(x, w_ff, b_ff, gamma, beta,
                                                 mean, var, out);
}

// round 10
// speedup vs baseline: 1.2373x; 1.2373x over previous
#include <cuda_runtime.h>
#include <cuda_fp16.h>
#include <math.h>
#include <stdint.h>

#define Nn   32
#define Cc   192
#define Tt   256
#define Vv   25
#define Ss   3
#define MID  64
#define TV   6400          /* T*V */
#define C3   576           /* 3*C */
#define KF   1600          /* MID*Vv flattened contraction for attention */

// Scratch (static device arrays; allocation-free per harness rules)
__device__ __half g_qk[(size_t)Nn * 2 * Ss * Tt * KF];   // Q,K fp16 [n][part][s][t][kf]
__device__ float  g_tokV[(size_t)Nn * Ss * Tt * KF];     // V fp32 token-major [n][s][t][j]
__device__ float  g_att[(size_t)Nn * Ss * Tt * Tt];      // [ns][t][q] (tf32-rounded)
__device__ float  g_y[(size_t)Nn * Cc * TV];             // [n][d][p] (tf32-rounded)

// ---------------------------------------------------------------------------
// helpers
// ---------------------------------------------------------------------------
__device__ __forceinline__ uint32_t f2tf32(float x) {
    uint32_t r;
    asm("cvt.rna.tf32.f32 %0, %1;" : "=r"(r) : "f"(x));
    return r;
}
__device__ __forceinline__ float rnd_tf32(float x) {
    return __uint_as_float(f2tf32(x));
}
__device__ __forceinline__ void mma_tf32(float* d, const uint32_t* a,
                                         uint32_t b0, uint32_t b1) {
    asm volatile(
        "mma.sync.aligned.m16n8k8.row.col.f32.tf32.tf32.f32 "
        "{%0,%1,%2,%3}, {%4,%5,%6,%7}, {%8,%9}, {%0,%1,%2,%3};"
        : "+f"(d[0]), "+f"(d[1]), "+f"(d[2]), "+f"(d[3])
        : "r"(a[0]), "r"(a[1]), "r"(a[2]), "r"(a[3]), "r"(b0), "r"(b1));
}
__device__ __forceinline__ void mma_f16(float* d, const uint32_t* a,
                                        uint32_t b0, uint32_t b1) {
    asm volatile(
        "mma.sync.aligned.m16n8k16.row.col.f32.f16.f16.f32 "
        "{%0,%1,%2,%3}, {%4,%5,%6,%7}, {%8,%9}, {%0,%1,%2,%3};"
        : "+f"(d[0]), "+f"(d[1]), "+f"(d[2]), "+f"(d[3])
        : "r"(a[0]), "r"(a[1]), "r"(a[2]), "r"(a[3]), "r"(b0), "r"(b1));
}
__device__ __forceinline__ uint32_t smem_u32(const void* p) {
    return (uint32_t)__cvta_generic_to_shared(p);
}
__device__ __forceinline__ void cp16(uint32_t dst, const void* src) {
    asm volatile("cp.async.cg.shared.global [%0], [%1], 16;"
                 :: "r"(dst), "l"(src));
}
#define CP_COMMIT() asm volatile("cp.async.commit_group;")
#define CP_WAITG1() asm volatile("cp.async.wait_group 1;" ::: "memory")

// ---------------------------------------------------------------------------
// TF32 fragment math (identical to R8).
// A tiles: [m][k] XOR-16: element (m,k) at m*16 + (k ^ 4*((m>>1)&3))
// B [k][n] tiles: row stride SBN, plain. Warp tile 32m x 64n, acc[2][8][4].
// ---------------------------------------------------------------------------
template <int SBN, bool CA, bool CB>
__device__ __forceinline__ void mma_AkBn(const float* __restrict__ As,
                                         const float* __restrict__ Bs,
                                         float acc[2][8][4],
                                         int m0, int n0, int g, int ltg) {
    const int xk = 4 * ((g >> 1) & 3);
#pragma unroll
    for (int k8 = 0; k8 < 16; k8 += 8) {
        const int ka = (k8 + ltg) ^ xk;
        const int kb = (k8 + ltg + 4) ^ xk;
        uint32_t a[2][4];
#pragma unroll
        for (int mt = 0; mt < 2; mt++) {
            const float* Ar = As + (m0 + mt * 16 + g) * 16;
            a[mt][0] = CA ? f2tf32(Ar[ka]) : __float_as_uint(Ar[ka]);
            a[mt][1] = CA ? f2tf32(Ar[128 + ka]) : __float_as_uint(Ar[128 + ka]);
            a[mt][2] = CA ? f2tf32(Ar[kb]) : __float_as_uint(Ar[kb]);
            a[mt][3] = CA ? f2tf32(Ar[128 + kb]) : __float_as_uint(Ar[128 + kb]);
        }
        const float* B0 = Bs + (k8 + ltg) * SBN + n0 + g;
        const float* B1 = Bs + (k8 + ltg + 4) * SBN + n0 + g;
#pragma unroll
        for (int nt = 0; nt < 8; nt++) {
            const uint32_t b0 = CB ? f2tf32(B0[nt * 8]) : __float_as_uint(B0[nt * 8]);
            const uint32_t b1 = CB ? f2tf32(B1[nt * 8]) : __float_as_uint(B1[nt * 8]);
            mma_tf32(acc[0][nt], a[0], b0, b1);
            mma_tf32(acc[1][nt], a[1], b0, b1);
        }
    }
}

// ---------------------------------------------------------------------------
// fp16 fragment math (validated R7/R8): [row][16 halves] = 8 b32/row;
// 16B granule u of row r stored at granule (u ^ ((r>>2)&1)).
// ---------------------------------------------------------------------------
__device__ __forceinline__ void mma16_chunk(const uint32_t* __restrict__ As,
                                            const uint32_t* __restrict__ Bs,
                                            float acc[2][8][4],
                                            int m0, int n0, int g, int ltg) {
    const int xk = 4 * ((g >> 2) & 1);
    const int ka = ltg + xk;
    const int kb = ltg + (xk ^ 4);
    uint32_t a[2][4];
#pragma unroll
    for (int mt = 0; mt < 2; mt++) {
        const uint32_t* Ar = As + (m0 + mt * 16 + g) * 8;
        a[mt][0] = Ar[ka];
        a[mt][1] = Ar[64 + ka];
        a[mt][2] = Ar[kb];
        a[mt][3] = Ar[64 + kb];
    }
#pragma unroll
    for (int nt = 0; nt < 8; nt++) {
        const uint32_t* Br = Bs + (n0 + nt * 8 + g) * 8;
        const uint32_t b0 = Br[ka];
        const uint32_t b1 = Br[kb];
        mma_f16(acc[0][nt], a[0], b0, b1);
        mma_f16(acc[1][nt], a[1], b0, b1);
    }
}
__device__ __forceinline__ int sw_off(int r, int au) {
    return r * 8 + (au ^ ((r >> 2) & 1)) * 4;
}

// ---------------------------------------------------------------------------
// Kernel 1: QKV projection (TF32 core, R8 numerics). 3-stage pipeline,
// single barrier per chunk. Dynamic smem.
// Epilogue: Q,K -> fp16 token-major; V -> fp32 token-major (tf32-rounded).
// ---------------------------------------------------------------------------
__global__ __launch_bounds__(256, 2) void k_qkv(const float* __restrict__ x,
                                                const float* __restrict__ w_in,
                                                const float* __restrict__ b_in) {
    extern __shared__ __align__(16) float dyn[];
    float* AsP = dyn;            // 3 x 1024
    float* BsP = dyn + 3 * 1024; // 3 x 4224
    const int n  = blockIdx.z;
    const int d0 = blockIdx.x * 64;
    const int p0 = blockIdx.y * 256;
    const int tid = threadIdx.x, warp = tid >> 5, lane = tid & 31;
    const int wm = warp >> 2, wn = warp & 3;
    const int g = lane >> 2, ltg = lane & 3;

    const float* xn = x + (size_t)n * Cc * TV;

    const int ar = tid >> 2, au = tid & 3;
    const int axc = 4 * (au ^ ((ar >> 1) & 3));
    const int br = tid >> 4, bc4 = (tid & 15) * 4;

    auto stage = [&](int buf, int k0) {
        cp16(smem_u32(AsP + buf * 1024 + ar * 16 + axc),
             &w_in[(size_t)(d0 + ar) * Cc + k0 + au * 4]);
        const float* src = &xn[(size_t)(k0 + br) * TV + p0 + bc4];
        float* dst = BsP + buf * 4224 + br * 264 + bc4;
#pragma unroll
        for (int u = 0; u < 4; u++)
            cp16(smem_u32(dst + u * 64), src + u * 64);
    };

    float acc[2][8][4] = {};
    const int NC = Cc / 16;   // 12
    stage(0, 0);  CP_COMMIT();
    stage(1, 16); CP_COMMIT();
#pragma unroll 1
    for (int c = 0; c < NC; c++) {
        CP_WAITG1();
        __syncthreads();
        if (c + 2 < NC) stage((c + 2) % 3, (c + 2) * 16);
        CP_COMMIT();
        const int b = c % 3;
        mma_AkBn<264, true, true>(AsP + b * 1024, BsP + b * 4224, acc,
                                  wm * 32, wn * 64, g, ltg);
    }

    const int part = d0 / Cc;           // 0=Q,1=K,2=V
    const int s = (d0 % Cc) / MID;
    if (part < 2) {
        __half* qk = g_qk + (((size_t)(n * 2 + part) * Ss + s) * Tt) * KF;
#pragma unroll
        for (int mt = 0; mt < 2; mt++)
#pragma unroll
            for (int half = 0; half < 2; half++) {
                const int cch = wm * 32 + mt * 16 + g + half * 8;
                const float bias = b_in[d0 + cch];
#pragma unroll
                for (int nt = 0; nt < 8; nt++)
#pragma unroll
                    for (int e = 0; e < 2; e++) {
                        const int p = p0 + wn * 64 + nt * 8 + ltg * 2 + e;
                        const int t = p / 25, v = p - t * 25;
                        qk[(size_t)t * KF + cch * 25 + v] =
                            __float2half(acc[mt][nt][half * 2 + e] + bias);
                    }
            }
    } else {
        float* vb = g_tokV + (((size_t)(n * Ss + s)) * Tt) * KF;
#pragma unroll
        for (int mt = 0; mt < 2; mt++)
#pragma unroll
            for (int half = 0; half < 2; half++) {
                const int cch = wm * 32 + mt * 16 + g + half * 8;
                const float bias = b_in[d0 + cch];
#pragma unroll
                for (int nt = 0; nt < 8; nt++)
#pragma unroll
                    for (int e = 0; e < 2; e++) {
                        const int p = p0 + wn * 64 + nt * 8 + ltg * 2 + e;
                        const int t = p / 25, v = p - t * 25;
                        vb[(size_t)t * KF + cch * 25 + v] =
                            rnd_tf32(acc[mt][nt][half * 2 + e] + bias);
                    }
            }
    }
}

// ---------------------------------------------------------------------------
// Kernel 2: att = tanh(Q K^T / 1600). fp16 MMA, fp32 output. 3-stage, static smem.
// ---------------------------------------------------------------------------
__global__ __launch_bounds__(256, 2) void k_att() {
    __shared__ __align__(16) uint32_t As[3][64 * 8];
    __shared__ __align__(16) uint32_t Bs[3][256 * 8];
    const int ns = blockIdx.z;
    const int n = ns / 3, s = ns - 3 * n;
    const int t0 = blockIdx.y * 64;
    const int tid = threadIdx.x, warp = tid >> 5, lane = tid & 31;
    const int wm = warp >> 2, wn = warp & 3;
    const int g = lane >> 2, ltg = lane & 3;

    const __half* Qb = g_qk + (((size_t)(n * 2 + 0) * Ss + s) * Tt) * KF;
    const __half* Kb = g_qk + (((size_t)(n * 2 + 1) * Ss + s) * Tt) * KF;

    const int r2 = tid >> 1, au = tid & 1;

    auto stage = [&](int buf, int k0) {
        if (tid < 128)
            cp16(smem_u32(&As[buf][sw_off(r2, au)]),
                 Qb + (size_t)(t0 + r2) * KF + k0 + au * 8);
#pragma unroll
        for (int i = 0; i < 2; i++) {
            const int q = r2 + 128 * i;
            cp16(smem_u32(&Bs[buf][sw_off(q, au)]),
                 Kb + (size_t)q * KF + k0 + au * 8);
        }
    };

    float acc[2][8][4] = {};
    const int NC = KF / 16;   // 100
    stage(0, 0);  CP_COMMIT();
    stage(1, 16); CP_COMMIT();
#pragma unroll 1
    for (int c = 0; c < NC; c++) {
        CP_WAITG1();
        __syncthreads();
        if (c + 2 < NC) stage((c + 2) % 3, (c + 2) * 16);
        CP_COMMIT();
        mma16_chunk(As[c % 3], Bs[c % 3], acc, wm * 32, wn * 64, g, ltg);
    }

    const float scale = 1.0f / (float)KF;
    float* arow = g_att + (size_t)ns * Tt * Tt;
#pragma unroll
    for (int mt = 0; mt < 2; mt++)
#pragma unroll
        for (int half = 0; half < 2; half++) {
            const int t = t0 + wm * 32 + mt * 16 + g + half * 8;
#pragma unroll
            for (int nt = 0; nt < 8; nt++) {
                const int q = wn * 64 + nt * 8 + ltg * 2;
                float2 o;
                o.x = rnd_tf32(tanhf(acc[mt][nt][half * 2 + 0] * scale));
                o.y = rnd_tf32(tanhf(acc[mt][nt][half * 2 + 1] * scale));
                *(float2*)&arow[(size_t)t * Tt + q] = o;
            }
        }
}

// ---------------------------------------------------------------------------
// Kernel 3: y = att @ V_t (TF32, R8 numerics). 3-stage, dynamic smem.
// Block 256(t, 8 warps) x 64(j), K=256.
// ---------------------------------------------------------------------------
__global__ __launch_bounds__(256, 2) void k_y() {
    extern __shared__ __align__(16) float dyn[];
    float* AsP = dyn;            // 3 x 4096
    float* BsP = dyn + 3 * 4096; // 3 x 1152
    const int ns = blockIdx.z;
    const int n = ns / 3, s = ns - 3 * n;
    const int j0 = blockIdx.x * 64;
    const int tid = threadIdx.x, warp = tid >> 5, lane = tid & 31;
    const int g = lane >> 2, ltg = lane & 3;

    const float* att = g_att + (size_t)ns * Tt * Tt;
    const float* Vb  = g_tokV + (((size_t)(n * Ss + s)) * Tt) * KF;

    const int ar = tid >> 2, au = tid & 3;
    const int axc = 4 * (au ^ ((ar >> 1) & 3));
    const int br = tid >> 4, bc4 = (tid & 15) * 4;

    auto stage = [&](int buf, int k0) {
#pragma unroll
        for (int i = 0; i < 4; i++) {
            const int t = ar + 64 * i;
            cp16(smem_u32(AsP + buf * 4096 + t * 16 + axc),
                 &att[(size_t)t * Tt + k0 + au * 4]);
        }
        cp16(smem_u32(BsP + buf * 1152 + br * 72 + bc4),
             &Vb[(size_t)(k0 + br) * KF + j0 + bc4]);
    };

    float acc[2][8][4] = {};
    const int NC = Tt / 16;   // 16
    stage(0, 0);  CP_COMMIT();
    stage(1, 16); CP_COMMIT();
#pragma unroll 1
    for (int c = 0; c < NC; c++) {
        CP_WAITG1();
        __syncthreads();
        if (c + 2 < NC) stage((c + 2) % 3, (c + 2) * 16);
        CP_COMMIT();
        const int b = c % 3;
        mma_AkBn<72, false, false>(AsP + b * 4096, BsP + b * 1152, acc,
                                   warp * 32, 0, g, ltg);
    }

    float* yb = g_y + (size_t)n * Cc * TV + (size_t)(s * MID) * TV;
#pragma unroll
    for (int mt = 0; mt < 2; mt++)
#pragma unroll
        for (int half = 0; half < 2; half++) {
            const int t = warp * 32 + mt * 16 + g + half * 8;
#pragma unroll
            for (int nt = 0; nt < 8; nt++)
#pragma unroll
                for (int e = 0; e < 2; e++) {
                    const int j = j0 + nt * 8 + ltg * 2 + e;
                    const int cch = j / 25, v = j - cch * 25;
                    yb[(size_t)cch * TV + t * 25 + v] =
                        rnd_tf32(acc[mt][nt][half * 2 + e]);
                }
        }
}

// ---------------------------------------------------------------------------
// Kernel 4: FF + BN + residual + LeakyReLU (TF32, R8 numerics). 3-stage,
// dynamic smem.
// ---------------------------------------------------------------------------
__global__ __launch_bounds__(256, 2) void k_ff(const float* __restrict__ x,
                                               const float* __restrict__ w_ff,
                                               const float* __restrict__ b_ff,
                                               const float* __restrict__ gamma,
                                               const float* __restrict__ beta,
                                               const float* __restrict__ mean,
                                               const float* __restrict__ var,
                                               float* __restrict__ out) {
    extern __shared__ __align__(16) float dyn[];
    float* AsP = dyn;            // 3 x 1024
    float* BsP = dyn + 3 * 1024; // 3 x 4224
    const int n  = blockIdx.z;
    const int d0 = blockIdx.x * 64;
    const int p0 = blockIdx.y * 256;
    const int tid = threadIdx.x, warp = tid >> 5, lane = tid & 31;
    const int wm = warp >> 2, wn = warp & 3;
    const int g = lane >> 2, ltg = lane & 3;

    const float* yn = g_y + (size_t)n * Cc * TV;

    const int ar = tid >> 2, au = tid & 3;
    const int axc = 4 * (au ^ ((ar >> 1) & 3));
    const int br = tid >> 4, bc4 = (tid & 15) * 4;

    auto stage = [&](int buf, int k0) {
        cp16(smem_u32(AsP + buf * 1024 + ar * 16 + axc),
             &w_ff[(size_t)(d0 + ar) * Cc + k0 + au * 4]);
        const float* src = &yn[(size_t)(k0 + br) * TV + p0 + bc4];
        float* dst = BsP + buf * 4224 + br * 264 + bc4;
#pragma unroll
        for (int u = 0; u < 4; u++)
            cp16(smem_u32(dst + u * 64), src + u * 64);
    };

    float acc[2][8][4] = {};
    const int NC = Cc / 16;   // 12
    stage(0, 0);  CP_COMMIT();
    stage(1, 16); CP_COMMIT();
#pragma unroll 1
    for (int c = 0; c < NC; c++) {
        CP_WAITG1();
        __syncthreads();
        if (c + 2 < NC) stage((c + 2) % 3, (c + 2) * 16);
        CP_COMMIT();
        const int b = c % 3;
        mma_AkBn<264, true, false>(AsP + b * 1024, BsP + b * 4224, acc,
                                   wm * 32, wn * 64, g, ltg);
    }

    const float* xn = x + (size_t)n * Cc * TV;
    float* on = out + (size_t)n * Cc * TV;
#pragma unroll
    for (int mt = 0; mt < 2; mt++)
#pragma unroll
        for (int half = 0; half < 2; half++) {
            const int d = d0 + wm * 32 + mt * 16 + g + half * 8;
            const float inv = gamma[d] * rsqrtf(var[d] + 1e-5f);
            const float add = (b_ff[d] - mean[d]) * inv + beta[d];
#pragma unroll
            for (int nt = 0; nt < 8; nt++) {
                const int p = p0 + wn * 64 + nt * 8 + ltg * 2;
                const size_t off = (size_t)d * TV + p;
                float2 xv = *(const float2*)&xn[off];
                float z0 = xv.x + acc[mt][nt][half * 2 + 0] * inv + add;
                float z1 = xv.y + acc[mt][nt][half * 2 + 1] * inv + add;
                float2 o;
                o.x = z0 >= 0.f ? z0 : 0.1f * z0;
                o.y = z1 >= 0.f ? z1 : 0.1f * z1;
                *(float2*)&on[off] = o;
            }
        }
}

// ---------------------------------------------------------------------------
extern "C" void kernel_launch(void* const* d_in, const int* in_sizes, int n_in,
                              void* d_out, int out_size) {
    (void)in_sizes; (void)n_in; (void)out_size;
    const float* x     = (const float*)d_in[0];
    const float* w_in  = (const float*)d_in[1];
    const float* b_in  = (const float*)d_in[2];
    const float* w_ff  = (const float*)d_in[3];
    const float* b_ff  = (const float*)d_in[4];
    const float* gamma = (const float*)d_in[5];
    const float* beta  = (const float*)d_in[6];
    const float* mean  = (const float*)d_in[7];
    const float* var   = (const float*)d_in[8];
    float* out = (float*)d_out;

    const int SM_QKV = (3 * 1024 + 3 * 4224) * 4;   // 62976 B
    const int SM_Y   = (3 * 4096 + 3 * 1152) * 4;   // 62976 B
    static bool attr_set = false;
    if (!attr_set) {
        cudaFuncSetAttribute(k_qkv, cudaFuncAttributeMaxDynamicSharedMemorySize, SM_QKV);
        cudaFuncSetAttribute(k_y,   cudaFuncAttributeMaxDynamicSharedMemorySize, SM_Y);
        cudaFuncSetAttribute(k_ff,  cudaFuncAttributeMaxDynamicSharedMemorySize, SM_QKV);
        attr_set = true;
    }

    k_qkv<<<dim3(C3 / 64, TV / 256, Nn), 256, SM_QKV>>>(x, w_in, b_in);
    k_att<<<dim3(1, Tt / 64, Nn * Ss), 256>>>();
    k_y  <<<dim3(KF / 64, 1, Nn * Ss), 256, SM_Y>>>();
    k_ff <<<dim3(Cc / 64, TV / 256, Nn), 256, SM_QKV>>>(x, w_ff, b_ff, gamma,
                                                        beta, mean, var, out);
}

// round 11
// speedup vs baseline: 1.3894x; 1.1229x over previous
#include <cuda_runtime.h>
#include <cuda_fp16.h>
#include <math.h>
#include <stdint.h>

#define Nn   32
#define Cc   192
#define Tt   256
#define Vv   25
#define Ss   3
#define MID  64
#define TV   6400          /* T*V */
#define C3   576           /* 3*C */
#define KF   1600          /* MID*Vv flattened contraction for attention */

// Scratch (static device arrays; allocation-free per harness rules)
__device__ __align__(16) __half g_xt16[(size_t)Nn * TV * Cc];        // x^T fp16 [n][p][c]
__device__ __align__(16) __half g_win16[C3 * Cc];                    // w_in fp16
__device__ __align__(16) __half g_qk[(size_t)Nn * 2 * Ss * Tt * KF]; // Q,K fp16 [n][part][s][t][kf]
__device__ __align__(16) __half g_vt16[(size_t)Nn * Ss * KF * Tt];   // V^T fp16 [n][s][j][t]
__device__ __align__(16) __half g_att16[(size_t)Nn * Ss * Tt * Tt];  // att fp16 [ns][t][q]
__device__ __align__(16) float  g_y[(size_t)Nn * Cc * TV];           // y fp32 [n][d][p] tf32-rounded

// ---------------------------------------------------------------------------
// helpers
// ---------------------------------------------------------------------------
__device__ __forceinline__ uint32_t f2tf32(float x) {
    uint32_t r;
    asm("cvt.rna.tf32.f32 %0, %1;" : "=r"(r) : "f"(x));
    return r;
}
__device__ __forceinline__ float rnd_tf32(float x) {
    return __uint_as_float(f2tf32(x));
}
__device__ __forceinline__ void mma_tf32(float* d, const uint32_t* a,
                                         uint32_t b0, uint32_t b1) {
    asm volatile(
        "mma.sync.aligned.m16n8k8.row.col.f32.tf32.tf32.f32 "
        "{%0,%1,%2,%3}, {%4,%5,%6,%7}, {%8,%9}, {%0,%1,%2,%3};"
        : "+f"(d[0]), "+f"(d[1]), "+f"(d[2]), "+f"(d[3])
        : "r"(a[0]), "r"(a[1]), "r"(a[2]), "r"(a[3]), "r"(b0), "r"(b1));
}
__device__ __forceinline__ void mma_f16(float* d, const uint32_t* a,
                                        uint32_t b0, uint32_t b1) {
    asm volatile(
        "mma.sync.aligned.m16n8k16.row.col.f32.f16.f16.f32 "
        "{%0,%1,%2,%3}, {%4,%5,%6,%7}, {%8,%9}, {%0,%1,%2,%3};"
        : "+f"(d[0]), "+f"(d[1]), "+f"(d[2]), "+f"(d[3])
        : "r"(a[0]), "r"(a[1]), "r"(a[2]), "r"(a[3]), "r"(b0), "r"(b1));
}
__device__ __forceinline__ uint32_t smem_u32(const void* p) {
    return (uint32_t)__cvta_generic_to_shared(p);
}
__device__ __forceinline__ void cp16(uint32_t dst, const void* src) {
    asm volatile("cp.async.cg.shared.global [%0], [%1], 16;"
                 :: "r"(dst), "l"(src));
}
#define CP_COMMIT() asm volatile("cp.async.commit_group;")
#define CP_WAITG1() asm volatile("cp.async.wait_group 1;" ::: "memory")

// ---------------------------------------------------------------------------
// fp16 tile format (validated R7-R10): [row][16 halves] = 8 b32/row;
// 16B granule u of row r stored at granule (u ^ ((r>>2)&1)).
// A rows [m][k], B rows [n][k]; warp tile 32m x 64n, BK=16, acc[2][8][4].
// ---------------------------------------------------------------------------
__device__ __forceinline__ void mma16_chunk(const uint32_t* __restrict__ As,
                                            const uint32_t* __restrict__ Bs,
                                            float acc[2][8][4],
                                            int m0, int n0, int g, int ltg) {
    const int xk = 4 * ((g >> 2) & 1);
    const int ka = ltg + xk;
    const int kb = ltg + (xk ^ 4);
    uint32_t a[2][4];
#pragma unroll
    for (int mt = 0; mt < 2; mt++) {
        const uint32_t* Ar = As + (m0 + mt * 16 + g) * 8;
        a[mt][0] = Ar[ka];
        a[mt][1] = Ar[64 + ka];
        a[mt][2] = Ar[kb];
        a[mt][3] = Ar[64 + kb];
    }
#pragma unroll
    for (int nt = 0; nt < 8; nt++) {
        const uint32_t* Br = Bs + (n0 + nt * 8 + g) * 8;
        const uint32_t b0 = Br[ka];
        const uint32_t b1 = Br[kb];
        mma_f16(acc[0][nt], a[0], b0, b1);
        mma_f16(acc[1][nt], a[1], b0, b1);
    }
}
__device__ __forceinline__ int sw_off(int r, int au) {
    return r * 8 + (au ^ ((r >> 2) & 1)) * 4;
}

// TF32 fragment math for k_ff (identical to R10).
template <int SBN, bool CA, bool CB>
__device__ __forceinline__ void mma_AkBn(const float* __restrict__ As,
                                         const float* __restrict__ Bs,
                                         float acc[2][8][4],
                                         int m0, int n0, int g, int ltg) {
    const int xk = 4 * ((g >> 1) & 3);
#pragma unroll
    for (int k8 = 0; k8 < 16; k8 += 8) {
        const int ka = (k8 + ltg) ^ xk;
        const int kb = (k8 + ltg + 4) ^ xk;
        uint32_t a[2][4];
#pragma unroll
        for (int mt = 0; mt < 2; mt++) {
            const float* Ar = As + (m0 + mt * 16 + g) * 16;
            a[mt][0] = CA ? f2tf32(Ar[ka]) : __float_as_uint(Ar[ka]);
            a[mt][1] = CA ? f2tf32(Ar[128 + ka]) : __float_as_uint(Ar[128 + ka]);
            a[mt][2] = CA ? f2tf32(Ar[kb]) : __float_as_uint(Ar[kb]);
            a[mt][3] = CA ? f2tf32(Ar[128 + kb]) : __float_as_uint(Ar[128 + kb]);
        }
        const float* B0 = Bs + (k8 + ltg) * SBN + n0 + g;
        const float* B1 = Bs + (k8 + ltg + 4) * SBN + n0 + g;
#pragma unroll
        for (int nt = 0; nt < 8; nt++) {
            const uint32_t b0 = CB ? f2tf32(B0[nt * 8]) : __float_as_uint(B0[nt * 8]);
            const uint32_t b1 = CB ? f2tf32(B1[nt * 8]) : __float_as_uint(B1[nt * 8]);
            mma_tf32(acc[0][nt], a[0], b0, b1);
            mma_tf32(acc[1][nt], a[1], b0, b1);
        }
    }
}

// ---------------------------------------------------------------------------
// Kernel 0a: w_in -> fp16.
// ---------------------------------------------------------------------------
__global__ void k_wcv(const float* __restrict__ w_in) {
    const int i = blockIdx.x * 256 + threadIdx.x;
    if (i < C3 * Cc) g_win16[i] = __float2half(w_in[i]);
}

// ---------------------------------------------------------------------------
// Kernel 0b: transpose-convert x [n][c][p] fp32 -> xt16 [n][p][c] fp16.
// (R9-proven.)
// ---------------------------------------------------------------------------
__global__ __launch_bounds__(256) void k_cvtx(const float* __restrict__ x) {
    __shared__ uint32_t sm[64 * 97];
    const int n = blockIdx.y, p0 = blockIdx.x * 64;
    const float* xn = x + (size_t)n * Cc * TV;
    for (int idx = threadIdx.x; idx < 96 * 64; idx += 256) {
        const int c2 = idx >> 6, p = idx & 63;
        const float f0 = xn[(size_t)(2 * c2) * TV + p0 + p];
        const float f1 = xn[(size_t)(2 * c2 + 1) * TV + p0 + p];
        const __half2 h = __floats2half2_rn(f0, f1);
        sm[p * 97 + c2] = *(const uint32_t*)&h;
    }
    __syncthreads();
    uint32_t* dst = (uint32_t*)g_xt16 + ((size_t)n * TV + p0) * (Cc / 2);
    for (int idx = threadIdx.x; idx < 64 * 96; idx += 256) {
        const int p = idx / 96, u = idx - p * 96;
        dst[(size_t)p * 96 + u] = sm[p * 97 + u];
    }
}

// ---------------------------------------------------------------------------
// Kernel 1: Q,K projection (fp16 MMA). Block 64(d over Q,K=384 rows) x 256(p).
// A = w_in16[d][c], B = xt16[p][c]. 3-stage pipeline.
// ---------------------------------------------------------------------------
__global__ __launch_bounds__(256, 2) void k_qkv(const float* __restrict__ b_in) {
    __shared__ __align__(16) uint32_t As[3][512];
    __shared__ __align__(16) uint32_t Bs[3][2048];
    const int n  = blockIdx.z;
    const int d0 = blockIdx.x * 64;      // 0..320 (Q,K only)
    const int p0 = blockIdx.y * 256;
    const int tid = threadIdx.x, warp = tid >> 5, lane = tid & 31;
    const int wm = warp >> 2, wn = warp & 3;
    const int g = lane >> 2, ltg = lane & 3;

    const int r2 = tid >> 1, au = tid & 1;

    auto stage = [&](int buf, int k0) {
        if (tid < 128)
            cp16(smem_u32(&As[buf][sw_off(r2, au)]),
                 g_win16 + (size_t)(d0 + r2) * Cc + k0 + au * 8);
#pragma unroll
        for (int i = 0; i < 2; i++) {
            const int p = r2 + 128 * i;
            cp16(smem_u32(&Bs[buf][sw_off(p, au)]),
                 g_xt16 + ((size_t)n * TV + p0 + p) * Cc + k0 + au * 8);
        }
    };

    float acc[2][8][4] = {};
    const int NC = Cc / 16;   // 12
    stage(0, 0);  CP_COMMIT();
    stage(1, 16); CP_COMMIT();
#pragma unroll 1
    for (int c = 0; c < NC; c++) {
        CP_WAITG1();
        __syncthreads();
        if (c + 2 < NC) stage((c + 2) % 3, (c + 2) * 16);
        CP_COMMIT();
        mma16_chunk(As[c % 3], Bs[c % 3], acc, wm * 32, wn * 64, g, ltg);
    }

    const int part = d0 / Cc;           // 0=Q, 1=K
    const int s = (d0 % Cc) / MID;
    __half* qk = g_qk + (((size_t)(n * 2 + part) * Ss + s) * Tt) * KF;
#pragma unroll
    for (int mt = 0; mt < 2; mt++)
#pragma unroll
        for (int half = 0; half < 2; half++) {
            const int cch = wm * 32 + mt * 16 + g + half * 8;
            const float bias = b_in[d0 + cch];
#pragma unroll
            for (int nt = 0; nt < 8; nt++)
#pragma unroll
                for (int e = 0; e < 2; e++) {
                    const int p = p0 + wn * 64 + nt * 8 + ltg * 2 + e;
                    const int t = p / 25, v = p - t * 25;
                    qk[(size_t)t * KF + cch * 25 + v] =
                        __float2half(acc[mt][nt][half * 2 + e] + bias);
                }
        }
}

// ---------------------------------------------------------------------------
// Kernel 1b: V projection -> V^T fp16 [j][t], coalesced.
// Block per (v, s, n): M=64 (c), N=256 (t; B rows p=25t+v), K=192.
// Output rows j=c*25+v are contiguous over all 256 t -> 512B coalesced stores.
// ---------------------------------------------------------------------------
__global__ __launch_bounds__(256, 2) void k_v(const float* __restrict__ b_in) {
    __shared__ __align__(16) union {
        struct { uint32_t As[3][512]; uint32_t Bs[3][2048]; } p;
        __half vt[64 * 264];
    } sm;
    const int v = blockIdx.x;     // 0..24
    const int s = blockIdx.y;     // 0..2
    const int n = blockIdx.z;
    const int tid = threadIdx.x, warp = tid >> 5, lane = tid & 31;
    const int wm = warp >> 2, wn = warp & 3;
    const int g = lane >> 2, ltg = lane & 3;

    const int wrow = 2 * Cc + s * MID;
    const __half* Wv = g_win16 + (size_t)wrow * Cc;
    const __half* Xt = g_xt16 + (size_t)n * TV * Cc;

    const int r2 = tid >> 1, au = tid & 1;

    auto stage = [&](int buf, int k0) {
        if (tid < 128)
            cp16(smem_u32(&sm.p.As[buf][sw_off(r2, au)]),
                 Wv + (size_t)r2 * Cc + k0 + au * 8);
#pragma unroll
        for (int i = 0; i < 2; i++) {
            const int t = r2 + 128 * i;
            cp16(smem_u32(&sm.p.Bs[buf][sw_off(t, au)]),
                 Xt + (size_t)(25 * t + v) * Cc + k0 + au * 8);
        }
    };

    float acc[2][8][4] = {};
    const int NC = Cc / 16;   // 12
    stage(0, 0);  CP_COMMIT();
    stage(1, 16); CP_COMMIT();
#pragma unroll 1
    for (int c = 0; c < NC; c++) {
        CP_WAITG1();
        __syncthreads();
        if (c + 2 < NC) stage((c + 2) % 3, (c + 2) * 16);
        CP_COMMIT();
        mma16_chunk(sm.p.As[c % 3], sm.p.Bs[c % 3], acc,
                    wm * 32, wn * 64, g, ltg);
    }
    __syncthreads();   // pipeline reads done before aliasing union as vt

    // acc -> smem vt[c][t] (half2 stores, conflict-free: banks 4g+ltg)
#pragma unroll
    for (int mt = 0; mt < 2; mt++)
#pragma unroll
        for (int half = 0; half < 2; half++) {
            const int c = wm * 32 + mt * 16 + g + half * 8;
            const float bias = b_in[wrow + c];
#pragma unroll
            for (int nt = 0; nt < 8; nt++) {
                const int t = wn * 64 + nt * 8 + ltg * 2;
                __half2 hv = __floats2half2_rn(
                    acc[mt][nt][half * 2 + 0] + bias,
                    acc[mt][nt][half * 2 + 1] + bias);
                *(__half2*)&sm.vt[c * 264 + t] = hv;
            }
        }
    __syncthreads();

    // coalesced write: V^T row j = c*25+v, 256 t = 128 b32 words
    __half* vb = g_vt16 + ((size_t)(n * Ss + s) * KF) * Tt;
    for (int idx = tid; idx < 64 * 128; idx += 256) {
        const int c = idx >> 7, w = idx & 127;
        const uint32_t val = *(const uint32_t*)&sm.vt[c * 264 + w * 2];
        ((uint32_t*)(vb + (size_t)(c * 25 + v) * Tt))[w] = val;
    }
}

// ---------------------------------------------------------------------------
// Kernel 2: att = tanh(Q K^T / 1600). fp16 MMA, fp16 output. 3-stage.
// ---------------------------------------------------------------------------
__global__ __launch_bounds__(256, 2) void k_att() {
    __shared__ __align__(16) uint32_t As[3][512];
    __shared__ __align__(16) uint32_t Bs[3][2048];
    const int ns = blockIdx.z;
    const int n = ns / 3, s = ns - 3 * n;
    const int t0 = blockIdx.y * 64;
    const int tid = threadIdx.x, warp = tid >> 5, lane = tid & 31;
    const int wm = warp >> 2, wn = warp & 3;
    const int g = lane >> 2, ltg = lane & 3;

    const __half* Qb = g_qk + (((size_t)(n * 2 + 0) * Ss + s) * Tt) * KF;
    const __half* Kb = g_qk + (((size_t)(n * 2 + 1) * Ss + s) * Tt) * KF;

    const int r2 = tid >> 1, au = tid & 1;

    auto stage = [&](int buf, int k0) {
        if (tid < 128)
            cp16(smem_u32(&As[buf][sw_off(r2, au)]),
                 Qb + (size_t)(t0 + r2) * KF + k0 + au * 8);
#pragma unroll
        for (int i = 0; i < 2; i++) {
            const int q = r2 + 128 * i;
            cp16(smem_u32(&Bs[buf][sw_off(q, au)]),
                 Kb + (size_t)q * KF + k0 + au * 8);
        }
    };

    float acc[2][8][4] = {};
    const int NC = KF / 16;   // 100
    stage(0, 0);  CP_COMMIT();
    stage(1, 16); CP_COMMIT();
#pragma unroll 1
    for (int c = 0; c < NC; c++) {
        CP_WAITG1();
        __syncthreads();
        if (c + 2 < NC) stage((c + 2) % 3, (c + 2) * 16);
        CP_COMMIT();
        mma16_chunk(As[c % 3], Bs[c % 3], acc, wm * 32, wn * 64, g, ltg);
    }

    const float scale = 1.0f / (float)KF;
    __half* arow = g_att16 + (size_t)ns * Tt * Tt;
#pragma unroll
    for (int mt = 0; mt < 2; mt++)
#pragma unroll
        for (int half = 0; half < 2; half++) {
            const int t = t0 + wm * 32 + mt * 16 + g + half * 8;
#pragma unroll
            for (int nt = 0; nt < 8; nt++) {
                const int q = wn * 64 + nt * 8 + ltg * 2;
                __half2 o = __floats2half2_rn(
                    tanhf(acc[mt][nt][half * 2 + 0] * scale),
                    tanhf(acc[mt][nt][half * 2 + 1] * scale));
                *(__half2*)&arow[(size_t)t * Tt + q] = o;
            }
        }
}

// ---------------------------------------------------------------------------
// Kernel 3: y = att @ V. fp16 MMA. A = att16[t][q], B = vt16[j][t(=q)].
// Block 256(t, 8 warps) x 64(j), K=256. Output fp32 y[d][p] (tf32-rounded).
// ---------------------------------------------------------------------------
__global__ __launch_bounds__(256, 2) void k_y() {
    __shared__ __align__(16) uint32_t As[3][2048];
    __shared__ __align__(16) uint32_t Bs[3][512];
    const int ns = blockIdx.z;
    const int n = ns / 3, s = ns - 3 * n;
    const int j0 = blockIdx.x * 64;
    const int tid = threadIdx.x, warp = tid >> 5, lane = tid & 31;
    const int g = lane >> 2, ltg = lane & 3;

    const __half* att = g_att16 + (size_t)ns * Tt * Tt;
    const __half* Vb  = g_vt16 + ((size_t)(n * Ss + s) * KF) * Tt;

    const int r2 = tid >> 1, au = tid & 1;

    auto stage = [&](int buf, int k0) {
#pragma unroll
        for (int i = 0; i < 2; i++) {
            const int t = r2 + 128 * i;
            cp16(smem_u32(&As[buf][sw_off(t, au)]),
                 att + (size_t)t * Tt + k0 + au * 8);
        }
        if (tid < 128)
            cp16(smem_u32(&Bs[buf][sw_off(r2, au)]),
                 Vb + (size_t)(j0 + r2) * Tt + k0 + au * 8);
    };

    float acc[2][8][4] = {};
    const int NC = Tt / 16;   // 16
    stage(0, 0);  CP_COMMIT();
    stage(1, 16); CP_COMMIT();
#pragma unroll 1
    for (int c = 0; c < NC; c++) {
        CP_WAITG1();
        __syncthreads();
        if (c + 2 < NC) stage((c + 2) % 3, (c + 2) * 16);
        CP_COMMIT();
        mma16_chunk(As[c % 3], Bs[c % 3], acc, warp * 32, 0, g, ltg);
    }

    float* yb = g_y + (size_t)n * Cc * TV + (size_t)(s * MID) * TV;
#pragma unroll
    for (int mt = 0; mt < 2; mt++)
#pragma unroll
        for (int half = 0; half < 2; half++) {
            const int t = warp * 32 + mt * 16 + g + half * 8;
#pragma unroll
            for (int nt = 0; nt < 8; nt++)
#pragma unroll
                for (int e = 0; e < 2; e++) {
                    const int j = j0 + nt * 8 + ltg * 2 + e;
                    const int cch = j / 25, v = j - cch * 25;
                    yb[(size_t)cch * TV + t * 25 + v] =
                        rnd_tf32(acc[mt][nt][half * 2 + e]);
                }
        }
}

// ---------------------------------------------------------------------------
// Kernel 4: FF + BN + residual + LeakyReLU (TF32, identical to R10).
// ---------------------------------------------------------------------------
__global__ __launch_bounds__(256, 2) void k_ff(const float* __restrict__ x,
                                               const float* __restrict__ w_ff,
                                               const float* __restrict__ b_ff,
                                               const float* __restrict__ gamma,
                                               const float* __restrict__ beta,
                                               const float* __restrict__ mean,
                                               const float* __restrict__ var,
                                               float* __restrict__ out) {
    extern __shared__ __align__(16) float dyn[];
    float* AsP = dyn;            // 3 x 1024
    float* BsP = dyn + 3 * 1024; // 3 x 4224
    const int n  = blockIdx.z;
    const int d0 = blockIdx.x * 64;
    const int p0 = blockIdx.y * 256;
    const int tid = threadIdx.x, warp = tid >> 5, lane = tid & 31;
    const int wm = warp >> 2, wn = warp & 3;
    const int g = lane >> 2, ltg = lane & 3;

    const float* yn = g_y + (size_t)n * Cc * TV;

    const int ar = tid >> 2, au = tid & 3;
    const int axc = 4 * (au ^ ((ar >> 1) & 3));
    const int br = tid >> 4, bc4 = (tid & 15) * 4;

    auto stage = [&](int buf, int k0) {
        cp16(smem_u32(AsP + buf * 1024 + ar * 16 + axc),
             &w_ff[(size_t)(d0 + ar) * Cc + k0 + au * 4]);
        const float* src = &yn[(size_t)(k0 + br) * TV + p0 + bc4];
        float* dst = BsP + buf * 4224 + br * 264 + bc4;
#pragma unroll
        for (int u = 0; u < 4; u++)
            cp16(smem_u32(dst + u * 64), src + u * 64);
    };

    float acc[2][8][4] = {};
    const int NC = Cc / 16;   // 12
    stage(0, 0);  CP_COMMIT();
    stage(1, 16); CP_COMMIT();
#pragma unroll 1
    for (int c = 0; c < NC; c++) {
        CP_WAITG1();
        __syncthreads();
        if (c + 2 < NC) stage((c + 2) % 3, (c + 2) * 16);
        CP_COMMIT();
        const int b = c % 3;
        mma_AkBn<264, true, false>(AsP + b * 1024, BsP + b * 4224, acc,
                                   wm * 32, wn * 64, g, ltg);
    }

    const float* xn = x + (size_t)n * Cc * TV;
    float* on = out + (size_t)n * Cc * TV;
#pragma unroll
    for (int mt = 0; mt < 2; mt++)
#pragma unroll
        for (int half = 0; half < 2; half++) {
            const int d = d0 + wm * 32 + mt * 16 + g + half * 8;
            const float inv = gamma[d] * rsqrtf(var[d] + 1e-5f);
            const float add = (b_ff[d] - mean[d]) * inv + beta[d];
#pragma unroll
            for (int nt = 0; nt < 8; nt++) {
                const int p = p0 + wn * 64 + nt * 8 + ltg * 2;
                const size_t off = (size_t)d * TV + p;
                float2 xv = *(const float2*)&xn[off];
                float z0 = xv.x + acc[mt][nt][half * 2 + 0] * inv + add;
                float z1 = xv.y + acc[mt][nt][half * 2 + 1] * inv + add;
                float2 o;
                o.x = z0 >= 0.f ? z0 : 0.1f * z0;
                o.y = z1 >= 0.f ? z1 : 0.1f * z1;
                *(float2*)&on[off] = o;
            }
        }
}

// ---------------------------------------------------------------------------
extern "C" void kernel_launch(void* const* d_in, const int* in_sizes, int n_in,
                              void* d_out, int out_size) {
    (void)in_sizes; (void)n_in; (void)out_size;
    const float* x     = (const float*)d_in[0];
    const float* w_in  = (const float*)d_in[1];
    const float* b_in  = (const float*)d_in[2];
    const float* w_ff  = (const float*)d_in[3];
    const float* b_ff  = (const float*)d_in[4];
    const float* gamma = (const float*)d_in[5];
    const float* beta  = (const float*)d_in[6];
    const float* mean  = (const float*)d_in[7];
    const float* var   = (const float*)d_in[8];
    float* out = (float*)d_out;

    const int SM_FF = (3 * 1024 + 3 * 4224) * 4;   // 62976 B
    static bool attr_set = false;
    if (!attr_set) {
        cudaFuncSetAttribute(k_ff, cudaFuncAttributeMaxDynamicSharedMemorySize, SM_FF);
        attr_set = true;
    }

    k_wcv <<<(C3 * Cc + 255) / 256, 256>>>(w_in);
    k_cvtx<<<dim3(TV / 64, Nn), 256>>>(x);
    k_qkv <<<dim3(2 * Cc / 64, TV / 256, Nn), 256>>>(b_in);
    k_v   <<<dim3(Vv, Ss, Nn), 256>>>(b_in);
    k_att <<<dim3(1, Tt / 64, Nn * Ss), 256>>>();
    k_y   <<<dim3(KF / 64, 1, Nn * Ss), 256>>>();
    k_ff  <<<dim3(Cc / 64, TV / 256, Nn), 256, SM_FF>>>(x, w_ff, b_ff, gamma,
                                                        beta, mean, var, out);
}

// round 12
// speedup vs baseline: 1.3936x; 1.0030x over previous
#include <cuda_runtime.h>
#include <cuda_fp16.h>
#include <math.h>
#include <stdint.h>

#define Nn   32
#define Cc   192
#define Tt   256
#define Vv   25
#define Ss   3
#define MID  64
#define TV   6400          /* T*V */
#define C3   576           /* 3*C */
#define KF   1600          /* MID*Vv flattened contraction for attention */

// Scratch (static device arrays; allocation-free per harness rules)
__device__ __align__(16) __half g_xt16[(size_t)Nn * TV * Cc];        // x^T fp16 [n][p][c]
__device__ __align__(16) __half g_win16[C3 * Cc];                    // w_in fp16
__device__ __align__(16) __half g_qk[(size_t)Nn * 2 * Ss * Tt * KF]; // Q,K fp16 [n][part][s][t][kf]
__device__ __align__(16) __half g_vt16[(size_t)Nn * Ss * KF * Tt];   // V^T fp16 [n][s][j][t]
__device__ __align__(16) __half g_att16[(size_t)Nn * Ss * Tt * Tt];  // att fp16 [ns][t][q]
__device__ __align__(16) float  g_y[(size_t)Nn * Cc * TV];           // y fp32 [n][d][p] tf32-rounded

// ---------------------------------------------------------------------------
// helpers
// ---------------------------------------------------------------------------
__device__ __forceinline__ uint32_t f2tf32(float x) {
    uint32_t r;
    asm("cvt.rna.tf32.f32 %0, %1;" : "=r"(r) : "f"(x));
    return r;
}
__device__ __forceinline__ float rnd_tf32(float x) {
    return __uint_as_float(f2tf32(x));
}
__device__ __forceinline__ void mma_tf32(float* d, const uint32_t* a,
                                         uint32_t b0, uint32_t b1) {
    asm volatile(
        "mma.sync.aligned.m16n8k8.row.col.f32.tf32.tf32.f32 "
        "{%0,%1,%2,%3}, {%4,%5,%6,%7}, {%8,%9}, {%0,%1,%2,%3};"
        : "+f"(d[0]), "+f"(d[1]), "+f"(d[2]), "+f"(d[3])
        : "r"(a[0]), "r"(a[1]), "r"(a[2]), "r"(a[3]), "r"(b0), "r"(b1));
}
__device__ __forceinline__ void mma_f16(float* d, const uint32_t* a,
                                        uint32_t b0, uint32_t b1) {
    asm volatile(
        "mma.sync.aligned.m16n8k16.row.col.f32.f16.f16.f32 "
        "{%0,%1,%2,%3}, {%4,%5,%6,%7}, {%8,%9}, {%0,%1,%2,%3};"
        : "+f"(d[0]), "+f"(d[1]), "+f"(d[2]), "+f"(d[3])
        : "r"(a[0]), "r"(a[1]), "r"(a[2]), "r"(a[3]), "r"(b0), "r"(b1));
}
__device__ __forceinline__ uint32_t smem_u32(const void* p) {
    return (uint32_t)__cvta_generic_to_shared(p);
}
__device__ __forceinline__ void cp16(uint32_t dst, const void* src) {
    asm volatile("cp.async.cg.shared.global [%0], [%1], 16;"
                 :: "r"(dst), "l"(src));
}
#define CP_COMMIT() asm volatile("cp.async.commit_group;")
#define CP_WAITG1() asm volatile("cp.async.wait_group 1;" ::: "memory")

// ---------------------------------------------------------------------------
// fp16 tile format (validated R7-R10): [row][16 halves] = 8 b32/row;
// 16B granule u of row r stored at granule (u ^ ((r>>2)&1)).
// A rows [m][k], B rows [n][k]; warp tile 32m x 64n, BK=16, acc[2][8][4].
// ---------------------------------------------------------------------------
__device__ __forceinline__ void mma16_chunk(const uint32_t* __restrict__ As,
                                            const uint32_t* __restrict__ Bs,
                                            float acc[2][8][4],
                                            int m0, int n0, int g, int ltg) {
    const int xk = 4 * ((g >> 2) & 1);
    const int ka = ltg + xk;
    const int kb = ltg + (xk ^ 4);
    uint32_t a[2][4];
#pragma unroll
    for (int mt = 0; mt < 2; mt++) {
        const uint32_t* Ar = As + (m0 + mt * 16 + g) * 8;
        a[mt][0] = Ar[ka];
        a[mt][1] = Ar[64 + ka];
        a[mt][2] = Ar[kb];
        a[mt][3] = Ar[64 + kb];
    }
#pragma unroll
    for (int nt = 0; nt < 8; nt++) {
        const uint32_t* Br = Bs + (n0 + nt * 8 + g) * 8;
        const uint32_t b0 = Br[ka];
        const uint32_t b1 = Br[kb];
        mma_f16(acc[0][nt], a[0], b0, b1);
        mma_f16(acc[1][nt], a[1], b0, b1);
    }
}
__device__ __forceinline__ int sw_off(int r, int au) {
    return r * 8 + (au ^ ((r >> 2) & 1)) * 4;
}

// TF32 fragment math for k_ff (identical to R10).
template <int SBN, bool CA, bool CB>
__device__ __forceinline__ void mma_AkBn(const float* __restrict__ As,
                                         const float* __restrict__ Bs,
                                         float acc[2][8][4],
                                         int m0, int n0, int g, int ltg) {
    const int xk = 4 * ((g >> 1) & 3);
#pragma unroll
    for (int k8 = 0; k8 < 16; k8 += 8) {
        const int ka = (k8 + ltg) ^ xk;
        const int kb = (k8 + ltg + 4) ^ xk;
        uint32_t a[2][4];
#pragma unroll
        for (int mt = 0; mt < 2; mt++) {
            const float* Ar = As + (m0 + mt * 16 + g) * 16;
            a[mt][0] = CA ? f2tf32(Ar[ka]) : __float_as_uint(Ar[ka]);
            a[mt][1] = CA ? f2tf32(Ar[128 + ka]) : __float_as_uint(Ar[128 + ka]);
            a[mt][2] = CA ? f2tf32(Ar[kb]) : __float_as_uint(Ar[kb]);
            a[mt][3] = CA ? f2tf32(Ar[128 + kb]) : __float_as_uint(Ar[128 + kb]);
        }
        const float* B0 = Bs + (k8 + ltg) * SBN + n0 + g;
        const float* B1 = Bs + (k8 + ltg + 4) * SBN + n0 + g;
#pragma unroll
        for (int nt = 0; nt < 8; nt++) {
            const uint32_t b0 = CB ? f2tf32(B0[nt * 8]) : __float_as_uint(B0[nt * 8]);
            const uint32_t b1 = CB ? f2tf32(B1[nt * 8]) : __float_as_uint(B1[nt * 8]);
            mma_tf32(acc[0][nt], a[0], b0, b1);
            mma_tf32(acc[1][nt], a[1], b0, b1);
        }
    }
}

// ---------------------------------------------------------------------------
// Kernel 0a: w_in -> fp16.
// ---------------------------------------------------------------------------
__global__ void k_wcv(const float* __restrict__ w_in) {
    const int i = blockIdx.x * 256 + threadIdx.x;
    if (i < C3 * Cc) g_win16[i] = __float2half(w_in[i]);
}

// ---------------------------------------------------------------------------
// Kernel 0b: transpose-convert x [n][c][p] fp32 -> xt16 [n][p][c] fp16.
// (R9-proven.)
// ---------------------------------------------------------------------------
__global__ __launch_bounds__(256) void k_cvtx(const float* __restrict__ x) {
    __shared__ uint32_t sm[64 * 97];
    const int n = blockIdx.y, p0 = blockIdx.x * 64;
    const float* xn = x + (size_t)n * Cc * TV;
    for (int idx = threadIdx.x; idx < 96 * 64; idx += 256) {
        const int c2 = idx >> 6, p = idx & 63;
        const float f0 = xn[(size_t)(2 * c2) * TV + p0 + p];
        const float f1 = xn[(size_t)(2 * c2 + 1) * TV + p0 + p];
        const __half2 h = __floats2half2_rn(f0, f1);
        sm[p * 97 + c2] = *(const uint32_t*)&h;
    }
    __syncthreads();
    uint32_t* dst = (uint32_t*)g_xt16 + ((size_t)n * TV + p0) * (Cc / 2);
    for (int idx = threadIdx.x; idx < 64 * 96; idx += 256) {
        const int p = idx / 96, u = idx - p * 96;
        dst[(size_t)p * 96 + u] = sm[p * 97 + u];
    }
}

// ---------------------------------------------------------------------------
// Kernel 1: Q,K projection (fp16 MMA). Block 64(d over Q,K=384 rows) x 256(p).
// A = w_in16[d][c], B = xt16[p][c]. 3-stage pipeline.
// ---------------------------------------------------------------------------
__global__ __launch_bounds__(256, 2) void k_qkv(const float* __restrict__ b_in) {
    __shared__ __align__(16) uint32_t As[3][512];
    __shared__ __align__(16) uint32_t Bs[3][2048];
    const int n  = blockIdx.z;
    const int d0 = blockIdx.x * 64;      // 0..320 (Q,K only)
    const int p0 = blockIdx.y * 256;
    const int tid = threadIdx.x, warp = tid >> 5, lane = tid & 31;
    const int wm = warp >> 2, wn = warp & 3;
    const int g = lane >> 2, ltg = lane & 3;

    const int r2 = tid >> 1, au = tid & 1;

    auto stage = [&](int buf, int k0) {
        if (tid < 128)
            cp16(smem_u32(&As[buf][sw_off(r2, au)]),
                 g_win16 + (size_t)(d0 + r2) * Cc + k0 + au * 8);
#pragma unroll
        for (int i = 0; i < 2; i++) {
            const int p = r2 + 128 * i;
            cp16(smem_u32(&Bs[buf][sw_off(p, au)]),
                 g_xt16 + ((size_t)n * TV + p0 + p) * Cc + k0 + au * 8);
        }
    };

    float acc[2][8][4] = {};
    const int NC = Cc / 16;   // 12
    stage(0, 0);  CP_COMMIT();
    stage(1, 16); CP_COMMIT();
#pragma unroll 1
    for (int c = 0; c < NC; c++) {
        CP_WAITG1();
        __syncthreads();
        if (c + 2 < NC) stage((c + 2) % 3, (c + 2) * 16);
        CP_COMMIT();
        mma16_chunk(As[c % 3], Bs[c % 3], acc, wm * 32, wn * 64, g, ltg);
    }

    const int part = d0 / Cc;           // 0=Q, 1=K
    const int s = (d0 % Cc) / MID;
    __half* qk = g_qk + (((size_t)(n * 2 + part) * Ss + s) * Tt) * KF;
#pragma unroll
    for (int mt = 0; mt < 2; mt++)
#pragma unroll
        for (int half = 0; half < 2; half++) {
            const int cch = wm * 32 + mt * 16 + g + half * 8;
            const float bias = b_in[d0 + cch];
#pragma unroll
            for (int nt = 0; nt < 8; nt++)
#pragma unroll
                for (int e = 0; e < 2; e++) {
                    const int p = p0 + wn * 64 + nt * 8 + ltg * 2 + e;
                    const int t = p / 25, v = p - t * 25;
                    qk[(size_t)t * KF + cch * 25 + v] =
                        __float2half(acc[mt][nt][half * 2 + e] + bias);
                }
        }
}

// ---------------------------------------------------------------------------
// Kernel 1b: V projection -> V^T fp16 [j][t], coalesced.
// Block per (v, s, n): M=64 (c), N=256 (t; B rows p=25t+v), K=192.
// Output rows j=c*25+v are contiguous over all 256 t -> 512B coalesced stores.
// ---------------------------------------------------------------------------
__global__ __launch_bounds__(256, 2) void k_v(const float* __restrict__ b_in) {
    __shared__ __align__(16) union {
        struct { uint32_t As[3][512]; uint32_t Bs[3][2048]; } p;
        __half vt[64 * 264];
    } sm;
    const int v = blockIdx.x;     // 0..24
    const int s = blockIdx.y;     // 0..2
    const int n = blockIdx.z;
    const int tid = threadIdx.x, warp = tid >> 5, lane = tid & 31;
    const int wm = warp >> 2, wn = warp & 3;
    const int g = lane >> 2, ltg = lane & 3;

    const int wrow = 2 * Cc + s * MID;
    const __half* Wv = g_win16 + (size_t)wrow * Cc;
    const __half* Xt = g_xt16 + (size_t)n * TV * Cc;

    const int r2 = tid >> 1, au = tid & 1;

    auto stage = [&](int buf, int k0) {
        if (tid < 128)
            cp16(smem_u32(&sm.p.As[buf][sw_off(r2, au)]),
                 Wv + (size_t)r2 * Cc + k0 + au * 8);
#pragma unroll
        for (int i = 0; i < 2; i++) {
            const int t = r2 + 128 * i;
            cp16(smem_u32(&sm.p.Bs[buf][sw_off(t, au)]),
                 Xt + (size_t)(25 * t + v) * Cc + k0 + au * 8);
        }
    };

    float acc[2][8][4] = {};
    const int NC = Cc / 16;   // 12
    stage(0, 0);  CP_COMMIT();
    stage(1, 16); CP_COMMIT();
#pragma unroll 1
    for (int c = 0; c < NC; c++) {
        CP_WAITG1();
        __syncthreads();
        if (c + 2 < NC) stage((c + 2) % 3, (c + 2) * 16);
        CP_COMMIT();
        mma16_chunk(sm.p.As[c % 3], sm.p.Bs[c % 3], acc,
                    wm * 32, wn * 64, g, ltg);
    }
    __syncthreads();   // pipeline reads done before aliasing union as vt

    // acc -> smem vt[c][t] (half2 stores, conflict-free: banks 4g+ltg)
#pragma unroll
    for (int mt = 0; mt < 2; mt++)
#pragma unroll
        for (int half = 0; half < 2; half++) {
            const int c = wm * 32 + mt * 16 + g + half * 8;
            const float bias = b_in[wrow + c];
#pragma unroll
            for (int nt = 0; nt < 8; nt++) {
                const int t = wn * 64 + nt * 8 + ltg * 2;
                __half2 hv = __floats2half2_rn(
                    acc[mt][nt][half * 2 + 0] + bias,
                    acc[mt][nt][half * 2 + 1] + bias);
                *(__half2*)&sm.vt[c * 264 + t] = hv;
            }
        }
    __syncthreads();

    // coalesced write: V^T row j = c*25+v, 256 t = 128 b32 words
    __half* vb = g_vt16 + ((size_t)(n * Ss + s) * KF) * Tt;
    for (int idx = tid; idx < 64 * 128; idx += 256) {
        const int c = idx >> 7, w = idx & 127;
        const uint32_t val = *(const uint32_t*)&sm.vt[c * 264 + w * 2];
        ((uint32_t*)(vb + (size_t)(c * 25 + v) * Tt))[w] = val;
    }
}

// ---------------------------------------------------------------------------
// Kernel 2: att = tanh(Q K^T / 1600). fp16 MMA, fp16 output. 3-stage.
// ---------------------------------------------------------------------------
__global__ __launch_bounds__(256, 2) void k_att() {
    __shared__ __align__(16) uint32_t As[3][512];
    __shared__ __align__(16) uint32_t Bs[3][2048];
    const int ns = blockIdx.z;
    const int n = ns / 3, s = ns - 3 * n;
    const int t0 = blockIdx.y * 64;
    const int tid = threadIdx.x, warp = tid >> 5, lane = tid & 31;
    const int wm = warp >> 2, wn = warp & 3;
    const int g = lane >> 2, ltg = lane & 3;

    const __half* Qb = g_qk + (((size_t)(n * 2 + 0) * Ss + s) * Tt) * KF;
    const __half* Kb = g_qk + (((size_t)(n * 2 + 1) * Ss + s) * Tt) * KF;

    const int r2 = tid >> 1, au = tid & 1;

    auto stage = [&](int buf, int k0) {
        if (tid < 128)
            cp16(smem_u32(&As[buf][sw_off(r2, au)]),
                 Qb + (size_t)(t0 + r2) * KF + k0 + au * 8);
#pragma unroll
        for (int i = 0; i < 2; i++) {
            const int q = r2 + 128 * i;
            cp16(smem_u32(&Bs[buf][sw_off(q, au)]),
                 Kb + (size_t)q * KF + k0 + au * 8);
        }
    };

    float acc[2][8][4] = {};
    const int NC = KF / 16;   // 100
    stage(0, 0);  CP_COMMIT();
    stage(1, 16); CP_COMMIT();
#pragma unroll 1
    for (int c = 0; c < NC; c++) {
        CP_WAITG1();
        __syncthreads();
        if (c + 2 < NC) stage((c + 2) % 3, (c + 2) * 16);
        CP_COMMIT();
        mma16_chunk(As[c % 3], Bs[c % 3], acc, wm * 32, wn * 64, g, ltg);
    }

    const float scale = 1.0f / (float)KF;
    __half* arow = g_att16 + (size_t)ns * Tt * Tt;
#pragma unroll
    for (int mt = 0; mt < 2; mt++)
#pragma unroll
        for (int half = 0; half < 2; half++) {
            const int t = t0 + wm * 32 + mt * 16 + g + half * 8;
#pragma unroll
            for (int nt = 0; nt < 8; nt++) {
                const int q = wn * 64 + nt * 8 + ltg * 2;
                __half2 o = __floats2half2_rn(
                    tanhf(acc[mt][nt][half * 2 + 0] * scale),
                    tanhf(acc[mt][nt][half * 2 + 1] * scale));
                *(__half2*)&arow[(size_t)t * Tt + q] = o;
            }
        }
}

// ---------------------------------------------------------------------------
// Kernel 3: y = att @ V. fp16 MMA. A = att16[t][q], B = vt16[j][t(=q)].
// Block 256(t, 8 warps) x 64(j), K=256. Output fp32 y[d][p] (tf32-rounded).
// ---------------------------------------------------------------------------
__global__ __launch_bounds__(256, 2) void k_y() {
    __shared__ __align__(16) uint32_t As[3][2048];
    __shared__ __align__(16) uint32_t Bs[3][512];
    const int ns = blockIdx.z;
    const int n = ns / 3, s = ns - 3 * n;
    const int j0 = blockIdx.x * 64;
    const int tid = threadIdx.x, warp = tid >> 5, lane = tid & 31;
    const int g = lane >> 2, ltg = lane & 3;

    const __half* att = g_att16 + (size_t)ns * Tt * Tt;
    const __half* Vb  = g_vt16 + ((size_t)(n * Ss + s) * KF) * Tt;

    const int r2 = tid >> 1, au = tid & 1;

    auto stage = [&](int buf, int k0) {
#pragma unroll
        for (int i = 0; i < 2; i++) {
            const int t = r2 + 128 * i;
            cp16(smem_u32(&As[buf][sw_off(t, au)]),
                 att + (size_t)t * Tt + k0 + au * 8);
        }
        if (tid < 128)
            cp16(smem_u32(&Bs[buf][sw_off(r2, au)]),
                 Vb + (size_t)(j0 + r2) * Tt + k0 + au * 8);
    };

    float acc[2][8][4] = {};
    const int NC = Tt / 16;   // 16
    stage(0, 0);  CP_COMMIT();
    stage(1, 16); CP_COMMIT();
#pragma unroll 1
    for (int c = 0; c < NC; c++) {
        CP_WAITG1();
        __syncthreads();
        if (c + 2 < NC) stage((c + 2) % 3, (c + 2) * 16);
        CP_COMMIT();
        mma16_chunk(As[c % 3], Bs[c % 3], acc, warp * 32, 0, g, ltg);
    }

    float* yb = g_y + (size_t)n * Cc * TV + (size_t)(s * MID) * TV;
#pragma unroll
    for (int mt = 0; mt < 2; mt++)
#pragma unroll
        for (int half = 0; half < 2; half++) {
            const int t = warp * 32 + mt * 16 + g + half * 8;
#pragma unroll
            for (int nt = 0; nt < 8; nt++)
#pragma unroll
                for (int e = 0; e < 2; e++) {
                    const int j = j0 + nt * 8 + ltg * 2 + e;
                    const int cch = j / 25, v = j - cch * 25;
                    yb[(size_t)cch * TV + t * 25 + v] =
                        rnd_tf32(acc[mt][nt][half * 2 + e]);
                }
        }
}

// ---------------------------------------------------------------------------
// Kernel 4: FF + BN + residual + LeakyReLU (TF32, identical to R10).
// ---------------------------------------------------------------------------
__global__ __launch_bounds__(256, 2) void k_ff(const float* __restrict__ x,
                                               const float* __restrict__ w_ff,
                                               const float* __restrict__ b_ff,
                                               const float* __restrict__ gamma,
                                               const float* __restrict__ beta,
                                               const float* __restrict__ mean,
                                               const float* __restrict__ var,
                                               float* __restrict__ out) {
    extern __shared__ __align__(16) float dyn[];
    float* AsP = dyn;            // 3 x 1024
    float* BsP = dyn + 3 * 1024; // 3 x 4224
    const int n  = blockIdx.z;
    const int d0 = blockIdx.x * 64;
    const int p0 = blockIdx.y * 256;
    const int tid = threadIdx.x, warp = tid >> 5, lane = tid & 31;
    const int wm = warp >> 2, wn = warp & 3;
    const int g = lane >> 2, ltg = lane & 3;

    const float* yn = g_y + (size_t)n * Cc * TV;

    const int ar = tid >> 2, au = tid & 3;
    const int axc = 4 * (au ^ ((ar >> 1) & 3));
    const int br = tid >> 4, bc4 = (tid & 15) * 4;

    auto stage = [&](int buf, int k0) {
        cp16(smem_u32(AsP + buf * 1024 + ar * 16 + axc),
             &w_ff[(size_t)(d0 + ar) * Cc + k0 + au * 4]);
        const float* src = &yn[(size_t)(k0 + br) * TV + p0 + bc4];
        float* dst = BsP + buf * 4224 + br * 264 + bc4;
#pragma unroll
        for (int u = 0; u < 4; u++)
            cp16(smem_u32(dst + u * 64), src + u * 64);
    };

    float acc[2][8][4] = {};
    const int NC = Cc / 16;   // 12
    stage(0, 0);  CP_COMMIT();
    stage(1, 16); CP_COMMIT();
#pragma unroll 1
    for (int c = 0; c < NC; c++) {
        CP_WAITG1();
        __syncthreads();
        if (c + 2 < NC) stage((c + 2) % 3, (c + 2) * 16);
        CP_COMMIT();
        const int b = c % 3;
        mma_AkBn<264, true, false>(AsP + b * 1024, BsP + b * 4224, acc,
                                   wm * 32, wn * 64, g, ltg);
    }

    const float* xn = x + (size_t)n * Cc * TV;
    float* on = out + (size_t)n * Cc * TV;
#pragma unroll
    for (int mt = 0; mt < 2; mt++)
#pragma unroll
        for (int half = 0; half < 2; half++) {
            const int d = d0 + wm * 32 + mt * 16 + g + half * 8;
            const float inv = gamma[d] * rsqrtf(var[d] + 1e-5f);
            const float add = (b_ff[d] - mean[d]) * inv + beta[d];
#pragma unroll
            for (int nt = 0; nt < 8; nt++) {
                const int p = p0 + wn * 64 + nt * 8 + ltg * 2;
                const size_t off = (size_t)d * TV + p;
                float2 xv = *(const float2*)&xn[off];
                float z0 = xv.x + acc[mt][nt][half * 2 + 0] * inv + add;
                float z1 = xv.y + acc[mt][nt][half * 2 + 1] * inv + add;
                float2 o;
                o.x = z0 >= 0.f ? z0 : 0.1f * z0;
                o.y = z1 >= 0.f ? z1 : 0.1f * z1;
                *(float2*)&on[off] = o;
            }
        }
}

// ---------------------------------------------------------------------------
extern "C" void kernel_launch(void* const* d_in, const int* in_sizes, int n_in,
                              void* d_out, int out_size) {
    (void)in_sizes; (void)n_in; (void)out_size;
    const float* x     = (const float*)d_in[0];
    const float* w_in  = (const float*)d_in[1];
    const float* b_in  = (const float*)d_in[2];
    const float* w_ff  = (const float*)d_in[3];
    const float* b_ff  = (const float*)d_in[4];
    const float* gamma = (const float*)d_in[5];
    const float* beta  = (const float*)d_in[6];
    const float* mean  = (const float*)d_in[7];
    const float* var   = (const float*)d_in[8];
    float* out = (float*)d_out;

    const int SM_FF = (3 * 1024 + 3 * 4224) * 4;   // 62976 B
    static bool attr_set = false;
    if (!attr_set) {
        cudaFuncSetAttribute(k_ff, cudaFuncAttributeMaxDynamicSharedMemorySize, SM_FF);
        attr_set = true;
    }

    k_wcv <<<(C3 * Cc + 255) / 256, 256>>>(w_in);
    k_cvtx<<<dim3(TV / 64, Nn), 256>>>(x);
    k_qkv <<<dim3(2 * Cc / 64, TV / 256, Nn), 256>>>(b_in);
    k_v   <<<dim3(Vv, Ss, Nn), 256>>>(b_in);
    k_att <<<dim3(1, Tt / 64, Nn * Ss), 256>>>();
    k_y   <<<dim3(KF / 64, 1, Nn * Ss), 256>>>();
    k_ff  <<<dim3(Cc / 64, TV / 256, Nn), 256, SM_FF>>>(x, w_ff, b_ff, gamma,
                                                        beta, mean, var, out);
}

// round 13
// speedup vs baseline: 1.5080x; 1.0821x over previous
#include <cuda_runtime.h>
#include <cuda_fp16.h>
#include <math.h>
#include <stdint.h>

#define Nn   32
#define Cc   192
#define Tt   256
#define Vv   25
#define Ss   3
#define MID  64
#define TV   6400          /* T*V */
#define C3   576           /* 3*C */
#define KF   1600          /* MID*Vv flattened contraction for attention */

// Scratch (static device arrays; allocation-free per harness rules)
__device__ __align__(16) __half g_xt16[(size_t)Nn * TV * Cc];        // x^T fp16 [n][p][c]
__device__ __align__(16) __half g_win16[C3 * Cc];                    // w_in fp16
__device__ __align__(16) __half g_wff16[Cc * Cc];                    // w_ff fp16
__device__ __align__(16) __half g_qk[(size_t)Nn * 2 * Ss * Tt * KF]; // Q,K fp16 [n][part][s][t][kf]
__device__ __align__(16) __half g_vt16[(size_t)Nn * Ss * KF * Tt];   // V^T fp16 [n][s][j][t]
__device__ __align__(16) __half g_att16[(size_t)Nn * Ss * Tt * Tt];  // att fp16 [ns][t][q]
__device__ __align__(16) __half g_yt16[(size_t)Nn * TV * Cc];        // y^T fp16 [n][p][d]

// ---------------------------------------------------------------------------
// helpers
// ---------------------------------------------------------------------------
__device__ __forceinline__ void mma_f16(float* d, const uint32_t* a,
                                        uint32_t b0, uint32_t b1) {
    asm volatile(
        "mma.sync.aligned.m16n8k16.row.col.f32.f16.f16.f32 "
        "{%0,%1,%2,%3}, {%4,%5,%6,%7}, {%8,%9}, {%0,%1,%2,%3};"
        : "+f"(d[0]), "+f"(d[1]), "+f"(d[2]), "+f"(d[3])
        : "r"(a[0]), "r"(a[1]), "r"(a[2]), "r"(a[3]), "r"(b0), "r"(b1));
}
__device__ __forceinline__ uint32_t smem_u32(const void* p) {
    return (uint32_t)__cvta_generic_to_shared(p);
}
__device__ __forceinline__ void cp16(uint32_t dst, const void* src) {
    asm volatile("cp.async.cg.shared.global [%0], [%1], 16;"
                 :: "r"(dst), "l"(src));
}
#define CP_COMMIT() asm volatile("cp.async.commit_group;")
#define CP_WAITG1() asm volatile("cp.async.wait_group 1;" ::: "memory")

// ---------------------------------------------------------------------------
// fp16 tile format (validated R7-R12): [row][16 halves] = 8 b32/row;
// 16B granule u of row r stored at granule (u ^ ((r>>2)&1)).
// A rows [m][k], B rows [n][k]; warp tile 32m x 64n, BK=16, acc[2][8][4].
// ---------------------------------------------------------------------------
__device__ __forceinline__ void mma16_chunk(const uint32_t* __restrict__ As,
                                            const uint32_t* __restrict__ Bs,
                                            float acc[2][8][4],
                                            int m0, int n0, int g, int ltg) {
    const int xk = 4 * ((g >> 2) & 1);
    const int ka = ltg + xk;
    const int kb = ltg + (xk ^ 4);
    uint32_t a[2][4];
#pragma unroll
    for (int mt = 0; mt < 2; mt++) {
        const uint32_t* Ar = As + (m0 + mt * 16 + g) * 8;
        a[mt][0] = Ar[ka];
        a[mt][1] = Ar[64 + ka];
        a[mt][2] = Ar[kb];
        a[mt][3] = Ar[64 + kb];
    }
#pragma unroll
    for (int nt = 0; nt < 8; nt++) {
        const uint32_t* Br = Bs + (n0 + nt * 8 + g) * 8;
        const uint32_t b0 = Br[ka];
        const uint32_t b1 = Br[kb];
        mma_f16(acc[0][nt], a[0], b0, b1);
        mma_f16(acc[1][nt], a[1], b0, b1);
    }
}
__device__ __forceinline__ int sw_off(int r, int au) {
    return r * 8 + (au ^ ((r >> 2) & 1)) * 4;
}

// ---------------------------------------------------------------------------
// Kernel 0a: weights -> fp16.
// ---------------------------------------------------------------------------
__global__ void k_wcv(const float* __restrict__ w_in,
                      const float* __restrict__ w_ff) {
    const int i = blockIdx.x * 256 + threadIdx.x;
    if (i < C3 * Cc) g_win16[i] = __float2half(w_in[i]);
    if (i < Cc * Cc) g_wff16[i] = __float2half(w_ff[i]);
}

// ---------------------------------------------------------------------------
// Kernel 0b: transpose-convert x [n][c][p] fp32 -> xt16 [n][p][c] fp16.
// ---------------------------------------------------------------------------
__global__ __launch_bounds__(256) void k_cvtx(const float* __restrict__ x) {
    __shared__ uint32_t sm[64 * 97];
    const int n = blockIdx.y, p0 = blockIdx.x * 64;
    const float* xn = x + (size_t)n * Cc * TV;
    for (int idx = threadIdx.x; idx < 96 * 64; idx += 256) {
        const int c2 = idx >> 6, p = idx & 63;
        const float f0 = xn[(size_t)(2 * c2) * TV + p0 + p];
        const float f1 = xn[(size_t)(2 * c2 + 1) * TV + p0 + p];
        const __half2 h = __floats2half2_rn(f0, f1);
        sm[p * 97 + c2] = *(const uint32_t*)&h;
    }
    __syncthreads();
    uint32_t* dst = (uint32_t*)g_xt16 + ((size_t)n * TV + p0) * (Cc / 2);
    for (int idx = threadIdx.x; idx < 64 * 96; idx += 256) {
        const int p = idx / 96, u = idx - p * 96;
        dst[(size_t)p * 96 + u] = sm[p * 97 + u];
    }
}

// ---------------------------------------------------------------------------
// Kernel 1: Q,K projection (fp16 MMA). Block 64(d over Q,K=384 rows) x 256(p).
// ---------------------------------------------------------------------------
__global__ __launch_bounds__(256, 2) void k_qkv(const float* __restrict__ b_in) {
    __shared__ __align__(16) uint32_t As[3][512];
    __shared__ __align__(16) uint32_t Bs[3][2048];
    const int n  = blockIdx.z;
    const int d0 = blockIdx.x * 64;      // 0..320 (Q,K only)
    const int p0 = blockIdx.y * 256;
    const int tid = threadIdx.x, warp = tid >> 5, lane = tid & 31;
    const int wm = warp >> 2, wn = warp & 3;
    const int g = lane >> 2, ltg = lane & 3;

    const int r2 = tid >> 1, au = tid & 1;

    auto stage = [&](int buf, int k0) {
        if (tid < 128)
            cp16(smem_u32(&As[buf][sw_off(r2, au)]),
                 g_win16 + (size_t)(d0 + r2) * Cc + k0 + au * 8);
#pragma unroll
        for (int i = 0; i < 2; i++) {
            const int p = r2 + 128 * i;
            cp16(smem_u32(&Bs[buf][sw_off(p, au)]),
                 g_xt16 + ((size_t)n * TV + p0 + p) * Cc + k0 + au * 8);
        }
    };

    float acc[2][8][4] = {};
    const int NC = Cc / 16;   // 12
    stage(0, 0);  CP_COMMIT();
    stage(1, 16); CP_COMMIT();
#pragma unroll 1
    for (int c = 0; c < NC; c++) {
        CP_WAITG1();
        __syncthreads();
        if (c + 2 < NC) stage((c + 2) % 3, (c + 2) * 16);
        CP_COMMIT();
        mma16_chunk(As[c % 3], Bs[c % 3], acc, wm * 32, wn * 64, g, ltg);
    }

    const int part = d0 / Cc;           // 0=Q, 1=K
    const int s = (d0 % Cc) / MID;
    __half* qk = g_qk + (((size_t)(n * 2 + part) * Ss + s) * Tt) * KF;
#pragma unroll
    for (int mt = 0; mt < 2; mt++)
#pragma unroll
        for (int half = 0; half < 2; half++) {
            const int cch = wm * 32 + mt * 16 + g + half * 8;
            const float bias = b_in[d0 + cch];
#pragma unroll
            for (int nt = 0; nt < 8; nt++)
#pragma unroll
                for (int e = 0; e < 2; e++) {
                    const int p = p0 + wn * 64 + nt * 8 + ltg * 2 + e;
                    const int t = p / 25, v = p - t * 25;
                    qk[(size_t)t * KF + cch * 25 + v] =
                        __float2half(acc[mt][nt][half * 2 + e] + bias);
                }
        }
}

// ---------------------------------------------------------------------------
// Kernel 1b: V projection -> V^T fp16 [j][t], coalesced (R12-proven).
// ---------------------------------------------------------------------------
__global__ __launch_bounds__(256, 2) void k_v(const float* __restrict__ b_in) {
    __shared__ __align__(16) union {
        struct { uint32_t As[3][512]; uint32_t Bs[3][2048]; } p;
        __half vt[64 * 264];
    } sm;
    const int v = blockIdx.x;     // 0..24
    const int s = blockIdx.y;     // 0..2
    const int n = blockIdx.z;
    const int tid = threadIdx.x, warp = tid >> 5, lane = tid & 31;
    const int wm = warp >> 2, wn = warp & 3;
    const int g = lane >> 2, ltg = lane & 3;

    const int wrow = 2 * Cc + s * MID;
    const __half* Wv = g_win16 + (size_t)wrow * Cc;
    const __half* Xt = g_xt16 + (size_t)n * TV * Cc;

    const int r2 = tid >> 1, au = tid & 1;

    auto stage = [&](int buf, int k0) {
        if (tid < 128)
            cp16(smem_u32(&sm.p.As[buf][sw_off(r2, au)]),
                 Wv + (size_t)r2 * Cc + k0 + au * 8);
#pragma unroll
        for (int i = 0; i < 2; i++) {
            const int t = r2 + 128 * i;
            cp16(smem_u32(&sm.p.Bs[buf][sw_off(t, au)]),
                 Xt + (size_t)(25 * t + v) * Cc + k0 + au * 8);
        }
    };

    float acc[2][8][4] = {};
    const int NC = Cc / 16;   // 12
    stage(0, 0);  CP_COMMIT();
    stage(1, 16); CP_COMMIT();
#pragma unroll 1
    for (int c = 0; c < NC; c++) {
        CP_WAITG1();
        __syncthreads();
        if (c + 2 < NC) stage((c + 2) % 3, (c + 2) * 16);
        CP_COMMIT();
        mma16_chunk(sm.p.As[c % 3], sm.p.Bs[c % 3], acc,
                    wm * 32, wn * 64, g, ltg);
    }
    __syncthreads();   // pipeline reads done before aliasing union as vt

#pragma unroll
    for (int mt = 0; mt < 2; mt++)
#pragma unroll
        for (int half = 0; half < 2; half++) {
            const int c = wm * 32 + mt * 16 + g + half * 8;
            const float bias = b_in[wrow + c];
#pragma unroll
            for (int nt = 0; nt < 8; nt++) {
                const int t = wn * 64 + nt * 8 + ltg * 2;
                __half2 hv = __floats2half2_rn(
                    acc[mt][nt][half * 2 + 0] + bias,
                    acc[mt][nt][half * 2 + 1] + bias);
                *(__half2*)&sm.vt[c * 264 + t] = hv;
            }
        }
    __syncthreads();

    __half* vb = g_vt16 + ((size_t)(n * Ss + s) * KF) * Tt;
    for (int idx = tid; idx < 64 * 128; idx += 256) {
        const int c = idx >> 7, w = idx & 127;
        const uint32_t val = *(const uint32_t*)&sm.vt[c * 264 + w * 2];
        ((uint32_t*)(vb + (size_t)(c * 25 + v) * Tt))[w] = val;
    }
}

// ---------------------------------------------------------------------------
// Kernel 2: att = tanh(Q K^T / 1600). fp16 MMA, fp16 output (R12-proven).
// ---------------------------------------------------------------------------
__global__ __launch_bounds__(256, 2) void k_att() {
    __shared__ __align__(16) uint32_t As[3][512];
    __shared__ __align__(16) uint32_t Bs[3][2048];
    const int ns = blockIdx.z;
    const int n = ns / 3, s = ns - 3 * n;
    const int t0 = blockIdx.y * 64;
    const int tid = threadIdx.x, warp = tid >> 5, lane = tid & 31;
    const int wm = warp >> 2, wn = warp & 3;
    const int g = lane >> 2, ltg = lane & 3;

    const __half* Qb = g_qk + (((size_t)(n * 2 + 0) * Ss + s) * Tt) * KF;
    const __half* Kb = g_qk + (((size_t)(n * 2 + 1) * Ss + s) * Tt) * KF;

    const int r2 = tid >> 1, au = tid & 1;

    auto stage = [&](int buf, int k0) {
        if (tid < 128)
            cp16(smem_u32(&As[buf][sw_off(r2, au)]),
                 Qb + (size_t)(t0 + r2) * KF + k0 + au * 8);
#pragma unroll
        for (int i = 0; i < 2; i++) {
            const int q = r2 + 128 * i;
            cp16(smem_u32(&Bs[buf][sw_off(q, au)]),
                 Kb + (size_t)q * KF + k0 + au * 8);
        }
    };

    float acc[2][8][4] = {};
    const int NC = KF / 16;   // 100
    stage(0, 0);  CP_COMMIT();
    stage(1, 16); CP_COMMIT();
#pragma unroll 1
    for (int c = 0; c < NC; c++) {
        CP_WAITG1();
        __syncthreads();
        if (c + 2 < NC) stage((c + 2) % 3, (c + 2) * 16);
        CP_COMMIT();
        mma16_chunk(As[c % 3], Bs[c % 3], acc, wm * 32, wn * 64, g, ltg);
    }

    const float scale = 1.0f / (float)KF;
    __half* arow = g_att16 + (size_t)ns * Tt * Tt;
#pragma unroll
    for (int mt = 0; mt < 2; mt++)
#pragma unroll
        for (int half = 0; half < 2; half++) {
            const int t = t0 + wm * 32 + mt * 16 + g + half * 8;
#pragma unroll
            for (int nt = 0; nt < 8; nt++) {
                const int q = wn * 64 + nt * 8 + ltg * 2;
                __half2 o = __floats2half2_rn(
                    tanhf(acc[mt][nt][half * 2 + 0] * scale),
                    tanhf(acc[mt][nt][half * 2 + 1] * scale));
                *(__half2*)&arow[(size_t)t * Tt + q] = o;
            }
        }
}

// ---------------------------------------------------------------------------
// Kernel 3: y = att @ V, one block per (n,s,v). fp16 MMA.
// M=256(t, 8 warps), N=64(c), K=256(q). A = att16[t][q], B = vt16[c*25+v][q].
// Epilogue: y^T fp16 [p=25t+v][d=s*64+c] — 64 contiguous halves per row.
// ---------------------------------------------------------------------------
__global__ __launch_bounds__(256, 2) void k_y() {
    __shared__ __align__(16) uint32_t As[3][2048];
    __shared__ __align__(16) uint32_t Bs[3][512];
    const int v  = blockIdx.x;    // 0..24
    const int ns = blockIdx.z;
    const int n = ns / 3, s = ns - 3 * n;
    const int tid = threadIdx.x, warp = tid >> 5, lane = tid & 31;
    const int g = lane >> 2, ltg = lane & 3;

    const __half* att = g_att16 + (size_t)ns * Tt * Tt;
    const __half* Vb  = g_vt16 + ((size_t)(n * Ss + s) * KF) * Tt;

    const int r2 = tid >> 1, au = tid & 1;

    auto stage = [&](int buf, int k0) {
#pragma unroll
        for (int i = 0; i < 2; i++) {
            const int t = r2 + 128 * i;
            cp16(smem_u32(&As[buf][sw_off(t, au)]),
                 att + (size_t)t * Tt + k0 + au * 8);
        }
        if (tid < 128)
            cp16(smem_u32(&Bs[buf][sw_off(r2, au)]),
                 Vb + (size_t)(r2 * 25 + v) * Tt + k0 + au * 8);
    };

    float acc[2][8][4] = {};
    const int NC = Tt / 16;   // 16
    stage(0, 0);  CP_COMMIT();
    stage(1, 16); CP_COMMIT();
#pragma unroll 1
    for (int c = 0; c < NC; c++) {
        CP_WAITG1();
        __syncthreads();
        if (c + 2 < NC) stage((c + 2) % 3, (c + 2) * 16);
        CP_COMMIT();
        mma16_chunk(As[c % 3], Bs[c % 3], acc, warp * 32, 0, g, ltg);
    }

    __half* yt = g_yt16 + (size_t)n * TV * Cc + s * MID;
#pragma unroll
    for (int mt = 0; mt < 2; mt++)
#pragma unroll
        for (int half = 0; half < 2; half++) {
            const int t = warp * 32 + mt * 16 + g + half * 8;
            __half* row = yt + (size_t)(t * 25 + v) * Cc;
#pragma unroll
            for (int nt = 0; nt < 8; nt++) {
                const int c = nt * 8 + ltg * 2;
                __half2 hv = __floats2half2_rn(
                    acc[mt][nt][half * 2 + 0],
                    acc[mt][nt][half * 2 + 1]);
                *(__half2*)&row[c] = hv;
            }
        }
}

// ---------------------------------------------------------------------------
// Kernel 4: FF + BN + residual + LeakyReLU, fp16 MMA.
// Block 64(d) x 256(p), K=192. A = wff16[d][c], B = yt16[p][c].
// ---------------------------------------------------------------------------
__global__ __launch_bounds__(256, 2) void k_ff(const float* __restrict__ x,
                                               const float* __restrict__ b_ff,
                                               const float* __restrict__ gamma,
                                               const float* __restrict__ beta,
                                               const float* __restrict__ mean,
                                               const float* __restrict__ var,
                                               float* __restrict__ out) {
    __shared__ __align__(16) uint32_t As[3][512];
    __shared__ __align__(16) uint32_t Bs[3][2048];
    const int n  = blockIdx.z;
    const int d0 = blockIdx.x * 64;
    const int p0 = blockIdx.y * 256;
    const int tid = threadIdx.x, warp = tid >> 5, lane = tid & 31;
    const int wm = warp >> 2, wn = warp & 3;
    const int g = lane >> 2, ltg = lane & 3;

    const __half* yt = g_yt16 + (size_t)n * TV * Cc;

    const int r2 = tid >> 1, au = tid & 1;

    auto stage = [&](int buf, int k0) {
        if (tid < 128)
            cp16(smem_u32(&As[buf][sw_off(r2, au)]),
                 g_wff16 + (size_t)(d0 + r2) * Cc + k0 + au * 8);
#pragma unroll
        for (int i = 0; i < 2; i++) {
            const int p = r2 + 128 * i;
            cp16(smem_u32(&Bs[buf][sw_off(p, au)]),
                 yt + (size_t)(p0 + p) * Cc + k0 + au * 8);
        }
    };

    float acc[2][8][4] = {};
    const int NC = Cc / 16;   // 12
    stage(0, 0);  CP_COMMIT();
    stage(1, 16); CP_COMMIT();
#pragma unroll 1
    for (int c = 0; c < NC; c++) {
        CP_WAITG1();
        __syncthreads();
        if (c + 2 < NC) stage((c + 2) % 3, (c + 2) * 16);
        CP_COMMIT();
        mma16_chunk(As[c % 3], Bs[c % 3], acc, wm * 32, wn * 64, g, ltg);
    }

    const float* xn = x + (size_t)n * Cc * TV;
    float* on = out + (size_t)n * Cc * TV;
#pragma unroll
    for (int mt = 0; mt < 2; mt++)
#pragma unroll
        for (int half = 0; half < 2; half++) {
            const int d = d0 + wm * 32 + mt * 16 + g + half * 8;
            const float inv = gamma[d] * rsqrtf(var[d] + 1e-5f);
            const float add = (b_ff[d] - mean[d]) * inv + beta[d];
#pragma unroll
            for (int nt = 0; nt < 8; nt++) {
                const int p = p0 + wn * 64 + nt * 8 + ltg * 2;
                const size_t off = (size_t)d * TV + p;
                float2 xv = *(const float2*)&xn[off];
                float z0 = xv.x + acc[mt][nt][half * 2 + 0] * inv + add;
                float z1 = xv.y + acc[mt][nt][half * 2 + 1] * inv + add;
                float2 o;
                o.x = z0 >= 0.f ? z0 : 0.1f * z0;
                o.y = z1 >= 0.f ? z1 : 0.1f * z1;
                *(float2*)&on[off] = o;
            }
        }
}

// ---------------------------------------------------------------------------
extern "C" void kernel_launch(void* const* d_in, const int* in_sizes, int n_in,
                              void* d_out, int out_size) {
    (void)in_sizes; (void)n_in; (void)out_size;
    const float* x     = (const float*)d_in[0];
    const float* w_in  = (const float*)d_in[1];
    const float* b_in  = (const float*)d_in[2];
    const float* w_ff  = (const float*)d_in[3];
    const float* b_ff  = (const float*)d_in[4];
    const float* gamma = (const float*)d_in[5];
    const float* beta  = (const float*)d_in[6];
    const float* mean  = (const float*)d_in[7];
    const float* var   = (const float*)d_in[8];
    float* out = (float*)d_out;

    k_wcv <<<(C3 * Cc + 255) / 256, 256>>>(w_in, w_ff);
    k_cvtx<<<dim3(TV / 64, Nn), 256>>>(x);
    k_qkv <<<dim3(2 * Cc / 64, TV / 256, Nn), 256>>>(b_in);
    k_v   <<<dim3(Vv, Ss, Nn), 256>>>(b_in);
    k_att <<<dim3(1, Tt / 64, Nn * Ss), 256>>>();
    k_y   <<<dim3(Vv, 1, Nn * Ss), 256>>>();
    k_ff  <<<dim3(Cc / 64, TV / 256, Nn), 256>>>(x, b_ff, gamma, beta,
                                                 mean, var, out);
}